// round 1
// baseline (speedup 1.0000x reference)
#include <cuda_runtime.h>
#include <cstdint>

// ---------------------------------------------------------------------------
// Fused ConditionedEdgeModel:
//   w  = relu(LN(winding @ Ww + bw))                       [E,128]
//   x  = concat(src, dest, edge_attr, u[batch], w)         [E,384]
//   h1 = relu(LN(x @ W1 + b1))                             [E,256]
//   h2 = relu(LN(h1 @ W2 + b2))                            [E,256]
//   out= h2 @ W3 + b3                                      [E,64]
// One CTA = 128 edges. TF32 mma.sync (m16n8k8) with fp32 accumulate.
// ---------------------------------------------------------------------------

namespace {

constexpr int LDA = 388;                 // 384 + 4 pad (bank-conflict-free A frags)
constexpr int LDH = 260;                 // 256 + 4 pad
constexpr int LDB = 264;                 // 256 + 8 pad (bank-conflict-free B frags)
constexpr int SM_A = 128 * LDA;          // 49664 floats (reused as h buffer)
constexpr int SM_B = 16 * LDB;           // 4224 floats
constexpr int SM_P = 2240;               // staged params
constexpr int SMEM_BYTES = (SM_A + SM_B + SM_P) * 4 + 128 * 4;  // 225024 B

// param offsets inside P[]
constexpr int P_WW = 0;      // Ww [2][128] row-major (256)
constexpr int P_BW = 256;    // bw (128)
constexpr int P_GW = 384;    // gw (128)
constexpr int P_BTW = 512;   // betaw (128)
constexpr int P_B1 = 640;    // b1 (256)
constexpr int P_G1 = 896;
constexpr int P_BT1 = 1152;
constexpr int P_B2 = 1408;
constexpr int P_G2 = 1664;
constexpr int P_BT2 = 1920;
constexpr int P_B3 = 2176;   // b3 (64)

__device__ int g_is64;       // batch dtype flag (1 = int64, 0 = int32)

__device__ __forceinline__ float f2tf(float f) {
    unsigned u;
    asm("cvt.rna.tf32.f32 %0, %1;" : "=r"(u) : "f"(f));
    return __uint_as_float(u);
}

__device__ __forceinline__ void mma8(float* d, const unsigned* a, unsigned b0, unsigned b1) {
    asm volatile(
        "mma.sync.aligned.m16n8k8.row.col.f32.tf32.tf32.f32 "
        "{%0,%1,%2,%3},{%4,%5,%6,%7},{%8,%9},{%0,%1,%2,%3};\n"
        : "+f"(d[0]), "+f"(d[1]), "+f"(d[2]), "+f"(d[3])
        : "r"(a[0]), "r"(a[1]), "r"(a[2]), "r"(a[3]), "r"(b0), "r"(b1));
}

// Generic smem-A x gmem-B (staged via smem) GEMM mainloop.
// A: [128, KDIM] tf32 in smem (stride lda). B: W row-major [KDIM, NCOLS] fp32 in gmem.
// Warp computes a (MT*16) x (NT*8) tile at (warpRow, warpCol).
template <int KDIM, int NCOLS, int MT, int NT>
__device__ __forceinline__ void gemm_loop(
    const float* __restrict__ As, int lda, float* __restrict__ Bs,
    const float* __restrict__ W, float (&acc)[MT][NT][4],
    int warpRow, int warpCol, int tid, int gid, int tig)
{
#pragma unroll 1
    for (int kc = 0; kc < KDIM; kc += 16) {
        __syncthreads();  // previous Bs chunk fully consumed / A ready on first iter
#pragma unroll
        for (int i = 0; i < (16 * NCOLS) / 256; i++) {
            int idx = tid + i * 256;
            int r = idx / NCOLS, c = idx % NCOLS;
            Bs[r * LDB + c] = f2tf(W[(kc + r) * NCOLS + c]);
        }
        __syncthreads();
#pragma unroll
        for (int k8 = 0; k8 < 16; k8 += 8) {
            unsigned a[MT][4];
#pragma unroll
            for (int mt = 0; mt < MT; mt++) {
                const float* ap = As + (warpRow + mt * 16) * lda + kc + k8;
                a[mt][0] = __float_as_uint(ap[gid * lda + tig]);
                a[mt][1] = __float_as_uint(ap[(gid + 8) * lda + tig]);
                a[mt][2] = __float_as_uint(ap[gid * lda + tig + 4]);
                a[mt][3] = __float_as_uint(ap[(gid + 8) * lda + tig + 4]);
            }
#pragma unroll
            for (int nt = 0; nt < NT; nt++) {
                int col = warpCol + nt * 8 + gid;
                unsigned b0 = __float_as_uint(Bs[(k8 + tig) * LDB + col]);
                unsigned b1 = __float_as_uint(Bs[(k8 + tig + 4) * LDB + col]);
#pragma unroll
                for (int mt = 0; mt < MT; mt++) mma8(acc[mt][nt], a[mt], b0, b1);
            }
        }
    }
}

// Write accumulators (+bias) into H [128, 256] (stride LDH), raw fp32.
template <int MT, int NT>
__device__ __forceinline__ void store_acc_bias(
    float* __restrict__ H, const float (&acc)[MT][NT][4], const float* __restrict__ bias,
    int warpRow, int warpCol, int gid, int tig)
{
#pragma unroll
    for (int mt = 0; mt < MT; mt++) {
#pragma unroll
        for (int nt = 0; nt < NT; nt++) {
            int r0 = warpRow + mt * 16 + gid;
            int c0 = warpCol + nt * 8 + 2 * tig;
            H[r0 * LDH + c0]           = acc[mt][nt][0] + bias[c0];
            H[r0 * LDH + c0 + 1]       = acc[mt][nt][1] + bias[c0 + 1];
            H[(r0 + 8) * LDH + c0]     = acc[mt][nt][2] + bias[c0];
            H[(r0 + 8) * LDH + c0 + 1] = acc[mt][nt][3] + bias[c0 + 1];
        }
    }
}

// In-place LayerNorm+ReLU over 256-wide rows of H; writes back tf32.
__device__ __forceinline__ void ln_relu_256(
    float* __restrict__ H, const float* __restrict__ g, const float* __restrict__ b,
    int warp, int lane)
{
#pragma unroll 1
    for (int rr = 0; rr < 16; rr++) {
        int r = warp * 16 + rr;
        float v[8], s = 0.f, s2 = 0.f;
#pragma unroll
        for (int j = 0; j < 8; j++) {
            float x = H[r * LDH + lane + 32 * j];
            v[j] = x; s += x; s2 += x * x;
        }
#pragma unroll
        for (int o = 16; o; o >>= 1) {
            s  += __shfl_xor_sync(0xffffffffu, s, o);
            s2 += __shfl_xor_sync(0xffffffffu, s2, o);
        }
        float mu   = s * (1.f / 256.f);
        float var  = fmaf(-mu, mu, s2 * (1.f / 256.f));
        float rstd = rsqrtf(var + 1e-5f);
#pragma unroll
        for (int j = 0; j < 8; j++) {
            int c = lane + 32 * j;
            float y = fmaxf((v[j] - mu) * rstd * g[c] + b[c], 0.f);
            H[r * LDH + c] = f2tf(y);
        }
    }
}

}  // namespace

// batch may arrive as int32 or int64 (jax x64 ambiguity). If int64, the high
// 32-bit word of every element is 0 (values < 1024). Checking 32 hi-words == 0
// misidentifies int32 only with prob (1/1024)^32.
__global__ void detect_batch_kernel(const int* __restrict__ b32) {
    if (threadIdx.x == 0) {
        int ok = 1;
        for (int i = 0; i < 32; i++)
            if (b32[2 * i + 1] != 0) { ok = 0; break; }
        g_is64 = ok;
    }
}

__global__ void __launch_bounds__(256, 1)
fused_edge_kernel(const float* __restrict__ src, const float* __restrict__ dst_,
                  const float* __restrict__ ea, const float* __restrict__ u,
                  const void* __restrict__ batch_raw, const float* __restrict__ winding,
                  const float* __restrict__ Ww, const float* __restrict__ bw,
                  const float* __restrict__ gw, const float* __restrict__ betaw,
                  const float* __restrict__ W1, const float* __restrict__ b1,
                  const float* __restrict__ g1, const float* __restrict__ beta1,
                  const float* __restrict__ W2, const float* __restrict__ b2,
                  const float* __restrict__ g2, const float* __restrict__ beta2,
                  const float* __restrict__ W3, const float* __restrict__ b3,
                  float* __restrict__ out, int E)
{
    extern __shared__ float sm[];
    float* As = sm;                    // [128, LDA] x-tile, reused as h [128, LDH]
    float* Bs = sm + SM_A;             // [16, LDB] weight chunk
    float* P  = sm + SM_A + SM_B;      // params
    int* bsm  = (int*)(P + SM_P);      // batch ids [128]

    const int tid  = threadIdx.x;
    const int warp = tid >> 5, lane = tid & 31;
    const int gid  = lane >> 2, tig = lane & 3;
    const int e0   = blockIdx.x * 128;
    const int is64 = g_is64;

    // ---- stage params + batch ids ----
    if (tid < 256) {
        P[P_WW + tid]  = Ww[tid];
        P[P_B1 + tid]  = b1[tid];  P[P_G1 + tid]  = g1[tid];  P[P_BT1 + tid] = beta1[tid];
        P[P_B2 + tid]  = b2[tid];  P[P_G2 + tid]  = g2[tid];  P[P_BT2 + tid] = beta2[tid];
    }
    if (tid < 128) {
        P[P_BW + tid]  = bw[tid];  P[P_GW + tid]  = gw[tid];  P[P_BTW + tid] = betaw[tid];
        int e = e0 + tid;
        int b = 0;
        if (e < E)
            b = is64 ? (int)((const long long*)batch_raw)[e] : ((const int*)batch_raw)[e];
        bsm[tid] = b;
    }
    if (tid < 64) P[P_B3 + tid] = b3[tid];

    // ---- stage src/dest/edge_attr into A (cols 0..191), tf32 ----
#pragma unroll 1
    for (int idx = tid; idx < 128 * 64; idx += 256) {
        int r = idx >> 6, c = idx & 63;
        int e = e0 + r;
        float vs = 0.f, vd = 0.f, ve = 0.f;
        if (e < E) {
            size_t o = (size_t)e * 64 + c;
            vs = src[o]; vd = dst_[o]; ve = ea[o];
        }
        As[r * LDA + c]        = f2tf(vs);
        As[r * LDA + 64 + c]   = f2tf(vd);
        As[r * LDA + 128 + c]  = f2tf(ve);
    }
    __syncthreads();  // bsm + P ready

    // ---- gather u[batch] into A (cols 192..255) ----
#pragma unroll 1
    for (int idx = tid; idx < 128 * 64; idx += 256) {
        int r = idx >> 6, c = idx & 63;
        float v = 0.f;
        if (e0 + r < E) v = u[(size_t)bsm[r] * 64 + c];
        As[r * LDA + 192 + c] = f2tf(v);
    }

    // ---- winding MLP -> A (cols 256..383): Linear(2->128) + LN + ReLU ----
#pragma unroll 1
    for (int rr = 0; rr < 16; rr++) {
        int r = warp * 16 + rr;
        int e = e0 + r;
        float w0 = 0.f, w1 = 0.f;
        if (e < E) { w0 = winding[(size_t)e * 2]; w1 = winding[(size_t)e * 2 + 1]; }
        float v[4], s = 0.f, s2 = 0.f;
#pragma unroll
        for (int j = 0; j < 4; j++) {
            int c = lane * 4 + j;
            float x = fmaf(w0, P[P_WW + c], fmaf(w1, P[P_WW + 128 + c], P[P_BW + c]));
            v[j] = x; s += x; s2 += x * x;
        }
#pragma unroll
        for (int o = 16; o; o >>= 1) {
            s  += __shfl_xor_sync(0xffffffffu, s, o);
            s2 += __shfl_xor_sync(0xffffffffu, s2, o);
        }
        float mu   = s * (1.f / 128.f);
        float var  = fmaf(-mu, mu, s2 * (1.f / 128.f));
        float rstd = rsqrtf(var + 1e-5f);
#pragma unroll
        for (int j = 0; j < 4; j++) {
            int c = lane * 4 + j;
            float y = fmaxf((v[j] - mu) * rstd * P[P_GW + c] + P[P_BTW + c], 0.f);
            if (e >= E) y = 0.f;
            As[r * LDA + 256 + c] = f2tf(y);
        }
    }
    // gemm_loop starts with __syncthreads() -> A fully visible

    const int wR = (warp >> 2) * 64;
    const int wC = (warp & 3) * 64;

    // ---- GEMM1: [128,384] x [384,256] ----
    float acc[4][8][4];
#pragma unroll
    for (int mt = 0; mt < 4; mt++)
#pragma unroll
        for (int nt = 0; nt < 8; nt++)
#pragma unroll
            for (int j = 0; j < 4; j++) acc[mt][nt][j] = 0.f;
    gemm_loop<384, 256, 4, 8>(As, LDA, Bs, W1, acc, wR, wC, tid, gid, tig);

    __syncthreads();
    store_acc_bias<4, 8>(As, acc, P + P_B1, wR, wC, gid, tig);
    __syncthreads();
    ln_relu_256(As, P + P_G1, P + P_BT1, warp, lane);

    // ---- GEMM2: [128,256] x [256,256] ----
#pragma unroll
    for (int mt = 0; mt < 4; mt++)
#pragma unroll
        for (int nt = 0; nt < 8; nt++)
#pragma unroll
            for (int j = 0; j < 4; j++) acc[mt][nt][j] = 0.f;
    gemm_loop<256, 256, 4, 8>(As, LDH, Bs, W2, acc, wR, wC, tid, gid, tig);

    __syncthreads();
    store_acc_bias<4, 8>(As, acc, P + P_B2, wR, wC, gid, tig);
    __syncthreads();
    ln_relu_256(As, P + P_G2, P + P_BT2, warp, lane);

    // ---- GEMM3: [128,256] x [256,64] ----
    float acc3[2][4][4];
#pragma unroll
    for (int mt = 0; mt < 2; mt++)
#pragma unroll
        for (int nt = 0; nt < 4; nt++)
#pragma unroll
            for (int j = 0; j < 4; j++) acc3[mt][nt][j] = 0.f;
    const int wR3 = (warp >> 1) * 32;
    const int wC3 = (warp & 1) * 32;
    gemm_loop<256, 64, 2, 4>(As, LDH, Bs, W3, acc3, wR3, wC3, tid, gid, tig);

    // ---- epilogue: + b3, store ----
#pragma unroll
    for (int mt = 0; mt < 2; mt++) {
#pragma unroll
        for (int nt = 0; nt < 4; nt++) {
            int r0 = wR3 + mt * 16 + gid;
            int c0 = wC3 + nt * 8 + 2 * tig;
            int e  = e0 + r0;
            if (e < E) {
                float2 v = make_float2(acc3[mt][nt][0] + P[P_B3 + c0],
                                       acc3[mt][nt][1] + P[P_B3 + c0 + 1]);
                *(float2*)(out + (size_t)e * 64 + c0) = v;
            }
            e = e0 + r0 + 8;
            if (e < E) {
                float2 v = make_float2(acc3[mt][nt][2] + P[P_B3 + c0],
                                       acc3[mt][nt][3] + P[P_B3 + c0 + 1]);
                *(float2*)(out + (size_t)e * 64 + c0) = v;
            }
        }
    }
}

extern "C" void kernel_launch(void* const* d_in, const int* in_sizes, int n_in,
                              void* d_out, int out_size)
{
    const float* src     = (const float*)d_in[0];
    const float* dst_    = (const float*)d_in[1];
    const float* ea      = (const float*)d_in[2];
    const float* u       = (const float*)d_in[3];
    const void*  batch   = d_in[4];
    const float* winding = (const float*)d_in[5];
    const float* Ww      = (const float*)d_in[6];
    const float* bw      = (const float*)d_in[7];
    const float* gw      = (const float*)d_in[8];
    const float* betaw   = (const float*)d_in[9];
    const float* W1      = (const float*)d_in[10];
    const float* b1      = (const float*)d_in[11];
    const float* g1      = (const float*)d_in[12];
    const float* beta1   = (const float*)d_in[13];
    const float* W2      = (const float*)d_in[14];
    const float* b2      = (const float*)d_in[15];
    const float* g2      = (const float*)d_in[16];
    const float* beta2   = (const float*)d_in[17];
    const float* W3      = (const float*)d_in[18];
    const float* b3      = (const float*)d_in[19];

    const int E = in_sizes[0] / 64;

    cudaFuncSetAttribute(fused_edge_kernel,
                         cudaFuncAttributeMaxDynamicSharedMemorySize, SMEM_BYTES);

    detect_batch_kernel<<<1, 32>>>((const int*)batch);

    const int grid = (E + 127) / 128;
    fused_edge_kernel<<<grid, 256, SMEM_BYTES>>>(
        src, dst_, ea, u, batch, winding,
        Ww, bw, gw, betaw,
        W1, b1, g1, beta1,
        W2, b2, g2, beta2,
        W3, b3,
        (float*)d_out, E);
}

// round 2
// speedup vs baseline: 1.4094x; 1.4094x over previous
#include <cuda_runtime.h>
#include <cstdint>

// ---------------------------------------------------------------------------
// Fused ConditionedEdgeModel (round 2: pipelined weight staging):
//   w  = relu(LN(winding @ Ww + bw))                       [E,128]
//   x  = concat(src, dest, edge_attr, u[batch], w)         [E,384]
//   h1 = relu(LN(x @ W1 + b1))                             [E,256]
//   h2 = relu(LN(h1 @ W2 + b2))                            [E,256]
//   out= h2 @ W3 + b3                                      [E,64]
// One CTA = 128 edges. TF32 mma.sync (m16n8k8) with fp32 accumulate.
// Weight chunks double-buffered through registers (LDG overlapped with MMA).
// ---------------------------------------------------------------------------

namespace {

constexpr int LDA = 388;                 // 384 + 4 pad (bank-conflict-free A frags)
constexpr int LDH = 260;                 // 256 + 4 pad
constexpr int LDB = 264;                 // 256 + 8 pad (bank-conflict-free B frags)
constexpr int SM_A = 128 * LDA;          // 49664 floats (reused as h buffer)
constexpr int SM_B = 16 * LDB;           // 4224 floats
constexpr int SM_P = 2240;               // staged params
constexpr int SMEM_BYTES = (SM_A + SM_B + SM_P) * 4 + 128 * 4;  // 225024 B

// param offsets inside P[]
constexpr int P_WW = 0;      // Ww [2][128] row-major (256)
constexpr int P_BW = 256;    // bw (128)
constexpr int P_GW = 384;    // gw (128)
constexpr int P_BTW = 512;   // betaw (128)
constexpr int P_B1 = 640;    // b1 (256)
constexpr int P_G1 = 896;
constexpr int P_BT1 = 1152;
constexpr int P_B2 = 1408;
constexpr int P_G2 = 1664;
constexpr int P_BT2 = 1920;
constexpr int P_B3 = 2176;   // b3 (64)

__device__ int g_is64;       // batch dtype flag (1 = int64, 0 = int32)

__device__ __forceinline__ float f2tf(float f) {
    unsigned u;
    asm("cvt.rna.tf32.f32 %0, %1;" : "=r"(u) : "f"(f));
    return __uint_as_float(u);
}

__device__ __forceinline__ void mma8(float* d, const unsigned* a, unsigned b0, unsigned b1) {
    asm volatile(
        "mma.sync.aligned.m16n8k8.row.col.f32.tf32.tf32.f32 "
        "{%0,%1,%2,%3},{%4,%5,%6,%7},{%8,%9},{%0,%1,%2,%3};\n"
        : "+f"(d[0]), "+f"(d[1]), "+f"(d[2]), "+f"(d[3])
        : "r"(a[0]), "r"(a[1]), "r"(a[2]), "r"(a[3]), "r"(b0), "r"(b1));
}

// smem-A x gmem-B GEMM mainloop with register-double-buffered weight chunks.
// A: [128, KDIM] tf32 in smem (stride lda). B: W row-major [KDIM, NCOLS] fp32 in gmem.
// Warp computes a (MT*16) x (NT*8) tile at (warpRow, warpCol).
// Chunk = 16 K-rows staged through Bs; next chunk's LDGs issued before the
// current chunk's MMA block so L2/DRAM latency overlaps tensor work.
template <int KDIM, int NCOLS, int MT, int NT>
__device__ __forceinline__ void gemm_loop(
    const float* __restrict__ As, int lda, float* __restrict__ Bs,
    const float* __restrict__ W, float (&acc)[MT][NT][4],
    int warpRow, int warpCol, int tid, int gid, int tig)
{
    constexpr int R4 = (16 * NCOLS) / 1024;  // float4 per thread per chunk
    constexpr int C4 = NCOLS / 4;            // float4 per row
    float4 rb[R4];

    // prologue: chunk 0
#pragma unroll
    for (int i = 0; i < R4; i++) {
        int idx4 = tid + i * 256;
        int r = idx4 / C4, c = (idx4 % C4) * 4;
        rb[i] = *(const float4*)(W + (size_t)r * NCOLS + c);
    }

#pragma unroll 1
    for (int kc = 0; kc < KDIM; kc += 16) {
        __syncthreads();  // previous Bs chunk fully consumed / A ready on first iter
#pragma unroll
        for (int i = 0; i < R4; i++) {
            int idx4 = tid + i * 256;
            int r = idx4 / C4, c = (idx4 % C4) * 4;
            float4 v = rb[i];
            float4 t = make_float4(f2tf(v.x), f2tf(v.y), f2tf(v.z), f2tf(v.w));
            *(float4*)(Bs + r * LDB + c) = t;
        }
        __syncthreads();

        // prefetch next chunk — latency hidden behind the MMA block below
        if (kc + 16 < KDIM) {
#pragma unroll
            for (int i = 0; i < R4; i++) {
                int idx4 = tid + i * 256;
                int r = idx4 / C4, c = (idx4 % C4) * 4;
                rb[i] = *(const float4*)(W + (size_t)(kc + 16 + r) * NCOLS + c);
            }
        }

#pragma unroll
        for (int k8 = 0; k8 < 16; k8 += 8) {
            unsigned a[MT][4];
#pragma unroll
            for (int mt = 0; mt < MT; mt++) {
                const float* ap = As + (warpRow + mt * 16) * lda + kc + k8;
                a[mt][0] = __float_as_uint(ap[gid * lda + tig]);
                a[mt][1] = __float_as_uint(ap[(gid + 8) * lda + tig]);
                a[mt][2] = __float_as_uint(ap[gid * lda + tig + 4]);
                a[mt][3] = __float_as_uint(ap[(gid + 8) * lda + tig + 4]);
            }
#pragma unroll
            for (int nt = 0; nt < NT; nt++) {
                int col = warpCol + nt * 8 + gid;
                unsigned b0 = __float_as_uint(Bs[(k8 + tig) * LDB + col]);
                unsigned b1 = __float_as_uint(Bs[(k8 + tig + 4) * LDB + col]);
#pragma unroll
                for (int mt = 0; mt < MT; mt++) mma8(acc[mt][nt], a[mt], b0, b1);
            }
        }
    }
}

// Write accumulators (+bias) into H [128, 256] (stride LDH), raw fp32.
template <int MT, int NT>
__device__ __forceinline__ void store_acc_bias(
    float* __restrict__ H, const float (&acc)[MT][NT][4], const float* __restrict__ bias,
    int warpRow, int warpCol, int gid, int tig)
{
#pragma unroll
    for (int mt = 0; mt < MT; mt++) {
#pragma unroll
        for (int nt = 0; nt < NT; nt++) {
            int r0 = warpRow + mt * 16 + gid;
            int c0 = warpCol + nt * 8 + 2 * tig;
            H[r0 * LDH + c0]           = acc[mt][nt][0] + bias[c0];
            H[r0 * LDH + c0 + 1]       = acc[mt][nt][1] + bias[c0 + 1];
            H[(r0 + 8) * LDH + c0]     = acc[mt][nt][2] + bias[c0];
            H[(r0 + 8) * LDH + c0 + 1] = acc[mt][nt][3] + bias[c0 + 1];
        }
    }
}

// In-place LayerNorm+ReLU over 256-wide rows of H; writes back tf32.
__device__ __forceinline__ void ln_relu_256(
    float* __restrict__ H, const float* __restrict__ g, const float* __restrict__ b,
    int warp, int lane)
{
#pragma unroll 1
    for (int rr = 0; rr < 16; rr++) {
        int r = warp * 16 + rr;
        float v[8], s = 0.f, s2 = 0.f;
#pragma unroll
        for (int j = 0; j < 8; j++) {
            float x = H[r * LDH + lane + 32 * j];
            v[j] = x; s += x; s2 += x * x;
        }
#pragma unroll
        for (int o = 16; o; o >>= 1) {
            s  += __shfl_xor_sync(0xffffffffu, s, o);
            s2 += __shfl_xor_sync(0xffffffffu, s2, o);
        }
        float mu   = s * (1.f / 256.f);
        float var  = fmaf(-mu, mu, s2 * (1.f / 256.f));
        float rstd = rsqrtf(var + 1e-5f);
#pragma unroll
        for (int j = 0; j < 8; j++) {
            int c = lane + 32 * j;
            float y = fmaxf((v[j] - mu) * rstd * g[c] + b[c], 0.f);
            H[r * LDH + c] = f2tf(y);
        }
    }
}

}  // namespace

// batch may arrive as int32 or int64 (jax x64 ambiguity). If int64, the high
// 32-bit word of every element is 0 (values < 1024). Checking 32 hi-words == 0
// misidentifies int32 only with prob (1/1024)^32.
__global__ void detect_batch_kernel(const int* __restrict__ b32) {
    if (threadIdx.x == 0) {
        int ok = 1;
        for (int i = 0; i < 32; i++)
            if (b32[2 * i + 1] != 0) { ok = 0; break; }
        g_is64 = ok;
    }
}

__global__ void __launch_bounds__(256, 1)
fused_edge_kernel(const float* __restrict__ src, const float* __restrict__ dst_,
                  const float* __restrict__ ea, const float* __restrict__ u,
                  const void* __restrict__ batch_raw, const float* __restrict__ winding,
                  const float* __restrict__ Ww, const float* __restrict__ bw,
                  const float* __restrict__ gw, const float* __restrict__ betaw,
                  const float* __restrict__ W1, const float* __restrict__ b1,
                  const float* __restrict__ g1, const float* __restrict__ beta1,
                  const float* __restrict__ W2, const float* __restrict__ b2,
                  const float* __restrict__ g2, const float* __restrict__ beta2,
                  const float* __restrict__ W3, const float* __restrict__ b3,
                  float* __restrict__ out, int E)
{
    extern __shared__ float sm[];
    float* As = sm;                    // [128, LDA] x-tile, reused as h [128, LDH]
    float* Bs = sm + SM_A;             // [16, LDB] weight chunk
    float* P  = sm + SM_A + SM_B;      // params
    int* bsm  = (int*)(P + SM_P);      // batch ids [128]

    const int tid  = threadIdx.x;
    const int warp = tid >> 5, lane = tid & 31;
    const int gid  = lane >> 2, tig = lane & 3;
    const int e0   = blockIdx.x * 128;
    const int is64 = g_is64;

    // ---- stage params + batch ids ----
    if (tid < 256) {
        P[P_WW + tid]  = Ww[tid];
        P[P_B1 + tid]  = b1[tid];  P[P_G1 + tid]  = g1[tid];  P[P_BT1 + tid] = beta1[tid];
        P[P_B2 + tid]  = b2[tid];  P[P_G2 + tid]  = g2[tid];  P[P_BT2 + tid] = beta2[tid];
    }
    if (tid < 128) {
        P[P_BW + tid]  = bw[tid];  P[P_GW + tid]  = gw[tid];  P[P_BTW + tid] = betaw[tid];
        int e = e0 + tid;
        int b = 0;
        if (e < E)
            b = is64 ? (int)((const long long*)batch_raw)[e] : ((const int*)batch_raw)[e];
        bsm[tid] = b;
    }
    if (tid < 64) P[P_B3 + tid] = b3[tid];

    // ---- stage src/dest/edge_attr into A (cols 0..191), tf32, float4 loads ----
#pragma unroll 1
    for (int idx = tid; idx < 128 * 16; idx += 256) {
        int r = idx >> 4, c = (idx & 15) * 4;
        int e = e0 + r;
        float4 vs = make_float4(0.f, 0.f, 0.f, 0.f), vd = vs, ve = vs;
        if (e < E) {
            size_t o = (size_t)e * 64 + c;
            vs = *(const float4*)(src + o);
            vd = *(const float4*)(dst_ + o);
            ve = *(const float4*)(ea + o);
        }
        *(float4*)(As + r * LDA + c) =
            make_float4(f2tf(vs.x), f2tf(vs.y), f2tf(vs.z), f2tf(vs.w));
        *(float4*)(As + r * LDA + 64 + c) =
            make_float4(f2tf(vd.x), f2tf(vd.y), f2tf(vd.z), f2tf(vd.w));
        *(float4*)(As + r * LDA + 128 + c) =
            make_float4(f2tf(ve.x), f2tf(ve.y), f2tf(ve.z), f2tf(ve.w));
    }
    __syncthreads();  // bsm + P ready

    // ---- gather u[batch] into A (cols 192..255), float4 ----
#pragma unroll 1
    for (int idx = tid; idx < 128 * 16; idx += 256) {
        int r = idx >> 4, c = (idx & 15) * 4;
        float4 v = make_float4(0.f, 0.f, 0.f, 0.f);
        if (e0 + r < E) v = *(const float4*)(u + (size_t)bsm[r] * 64 + c);
        *(float4*)(As + r * LDA + 192 + c) =
            make_float4(f2tf(v.x), f2tf(v.y), f2tf(v.z), f2tf(v.w));
    }

    // ---- winding MLP -> A (cols 256..383): Linear(2->128) + LN + ReLU ----
#pragma unroll 1
    for (int rr = 0; rr < 16; rr++) {
        int r = warp * 16 + rr;
        int e = e0 + r;
        float w0 = 0.f, w1 = 0.f;
        if (e < E) { w0 = winding[(size_t)e * 2]; w1 = winding[(size_t)e * 2 + 1]; }
        float v[4], s = 0.f, s2 = 0.f;
#pragma unroll
        for (int j = 0; j < 4; j++) {
            int c = lane * 4 + j;
            float x = fmaf(w0, P[P_WW + c], fmaf(w1, P[P_WW + 128 + c], P[P_BW + c]));
            v[j] = x; s += x; s2 += x * x;
        }
#pragma unroll
        for (int o = 16; o; o >>= 1) {
            s  += __shfl_xor_sync(0xffffffffu, s, o);
            s2 += __shfl_xor_sync(0xffffffffu, s2, o);
        }
        float mu   = s * (1.f / 128.f);
        float var  = fmaf(-mu, mu, s2 * (1.f / 128.f));
        float rstd = rsqrtf(var + 1e-5f);
#pragma unroll
        for (int j = 0; j < 4; j++) {
            int c = lane * 4 + j;
            float y = fmaxf((v[j] - mu) * rstd * P[P_GW + c] + P[P_BTW + c], 0.f);
            if (e >= E) y = 0.f;
            As[r * LDA + 256 + c] = f2tf(y);
        }
    }
    // gemm_loop starts with __syncthreads() -> A fully visible

    const int wR = (warp >> 2) * 64;
    const int wC = (warp & 3) * 64;

    // ---- GEMM1: [128,384] x [384,256] ----
    float acc[4][8][4];
#pragma unroll
    for (int mt = 0; mt < 4; mt++)
#pragma unroll
        for (int nt = 0; nt < 8; nt++)
#pragma unroll
            for (int j = 0; j < 4; j++) acc[mt][nt][j] = 0.f;
    gemm_loop<384, 256, 4, 8>(As, LDA, Bs, W1, acc, wR, wC, tid, gid, tig);

    __syncthreads();
    store_acc_bias<4, 8>(As, acc, P + P_B1, wR, wC, gid, tig);
    __syncthreads();
    ln_relu_256(As, P + P_G1, P + P_BT1, warp, lane);

    // ---- GEMM2: [128,256] x [256,256] ----
#pragma unroll
    for (int mt = 0; mt < 4; mt++)
#pragma unroll
        for (int nt = 0; nt < 8; nt++)
#pragma unroll
            for (int j = 0; j < 4; j++) acc[mt][nt][j] = 0.f;
    gemm_loop<256, 256, 4, 8>(As, LDH, Bs, W2, acc, wR, wC, tid, gid, tig);

    __syncthreads();
    store_acc_bias<4, 8>(As, acc, P + P_B2, wR, wC, gid, tig);
    __syncthreads();
    ln_relu_256(As, P + P_G2, P + P_BT2, warp, lane);

    // ---- GEMM3: [128,256] x [256,64] ----
    float acc3[2][4][4];
#pragma unroll
    for (int mt = 0; mt < 2; mt++)
#pragma unroll
        for (int nt = 0; nt < 4; nt++)
#pragma unroll
            for (int j = 0; j < 4; j++) acc3[mt][nt][j] = 0.f;
    const int wR3 = (warp >> 1) * 32;
    const int wC3 = (warp & 1) * 32;
    gemm_loop<256, 64, 2, 4>(As, LDH, Bs, W3, acc3, wR3, wC3, tid, gid, tig);

    // ---- epilogue: + b3, store ----
#pragma unroll
    for (int mt = 0; mt < 2; mt++) {
#pragma unroll
        for (int nt = 0; nt < 4; nt++) {
            int r0 = wR3 + mt * 16 + gid;
            int c0 = wC3 + nt * 8 + 2 * tig;
            int e  = e0 + r0;
            if (e < E) {
                float2 v = make_float2(acc3[mt][nt][0] + P[P_B3 + c0],
                                       acc3[mt][nt][1] + P[P_B3 + c0 + 1]);
                *(float2*)(out + (size_t)e * 64 + c0) = v;
            }
            e = e0 + r0 + 8;
            if (e < E) {
                float2 v = make_float2(acc3[mt][nt][2] + P[P_B3 + c0],
                                       acc3[mt][nt][3] + P[P_B3 + c0 + 1]);
                *(float2*)(out + (size_t)e * 64 + c0) = v;
            }
        }
    }
}

extern "C" void kernel_launch(void* const* d_in, const int* in_sizes, int n_in,
                              void* d_out, int out_size)
{
    const float* src     = (const float*)d_in[0];
    const float* dst_    = (const float*)d_in[1];
    const float* ea      = (const float*)d_in[2];
    const float* u       = (const float*)d_in[3];
    const void*  batch   = d_in[4];
    const float* winding = (const float*)d_in[5];
    const float* Ww      = (const float*)d_in[6];
    const float* bw      = (const float*)d_in[7];
    const float* gw      = (const float*)d_in[8];
    const float* betaw   = (const float*)d_in[9];
    const float* W1      = (const float*)d_in[10];
    const float* b1      = (const float*)d_in[11];
    const float* g1      = (const float*)d_in[12];
    const float* beta1   = (const float*)d_in[13];
    const float* W2      = (const float*)d_in[14];
    const float* b2      = (const float*)d_in[15];
    const float* g2      = (const float*)d_in[16];
    const float* beta2   = (const float*)d_in[17];
    const float* W3      = (const float*)d_in[18];
    const float* b3      = (const float*)d_in[19];

    const int E = in_sizes[0] / 64;

    cudaFuncSetAttribute(fused_edge_kernel,
                         cudaFuncAttributeMaxDynamicSharedMemorySize, SMEM_BYTES);

    detect_batch_kernel<<<1, 32>>>((const int*)batch);

    const int grid = (E + 127) / 128;
    fused_edge_kernel<<<grid, 256, SMEM_BYTES>>>(
        src, dst_, ea, u, batch, winding,
        Ww, bw, gw, betaw,
        W1, b1, g1, beta1,
        W2, b2, g2, beta2,
        W3, b3,
        (float*)d_out, E);
}

// round 3
// speedup vs baseline: 1.4095x; 1.0000x over previous
#include <cuda_runtime.h>
#include <cstdint>

// ---------------------------------------------------------------------------
// Fused ConditionedEdgeModel (round 2: pipelined weight staging):
//   w  = relu(LN(winding @ Ww + bw))                       [E,128]
//   x  = concat(src, dest, edge_attr, u[batch], w)         [E,384]
//   h1 = relu(LN(x @ W1 + b1))                             [E,256]
//   h2 = relu(LN(h1 @ W2 + b2))                            [E,256]
//   out= h2 @ W3 + b3                                      [E,64]
// One CTA = 128 edges. TF32 mma.sync (m16n8k8) with fp32 accumulate.
// Weight chunks double-buffered through registers (LDG overlapped with MMA).
// ---------------------------------------------------------------------------

namespace {

constexpr int LDA = 388;                 // 384 + 4 pad (bank-conflict-free A frags)
constexpr int LDH = 260;                 // 256 + 4 pad
constexpr int LDB = 264;                 // 256 + 8 pad (bank-conflict-free B frags)
constexpr int SM_A = 128 * LDA;          // 49664 floats (reused as h buffer)
constexpr int SM_B = 16 * LDB;           // 4224 floats
constexpr int SM_P = 2240;               // staged params
constexpr int SMEM_BYTES = (SM_A + SM_B + SM_P) * 4 + 128 * 4;  // 225024 B

// param offsets inside P[]
constexpr int P_WW = 0;      // Ww [2][128] row-major (256)
constexpr int P_BW = 256;    // bw (128)
constexpr int P_GW = 384;    // gw (128)
constexpr int P_BTW = 512;   // betaw (128)
constexpr int P_B1 = 640;    // b1 (256)
constexpr int P_G1 = 896;
constexpr int P_BT1 = 1152;
constexpr int P_B2 = 1408;
constexpr int P_G2 = 1664;
constexpr int P_BT2 = 1920;
constexpr int P_B3 = 2176;   // b3 (64)

__device__ int g_is64;       // batch dtype flag (1 = int64, 0 = int32)

__device__ __forceinline__ float f2tf(float f) {
    unsigned u;
    asm("cvt.rna.tf32.f32 %0, %1;" : "=r"(u) : "f"(f));
    return __uint_as_float(u);
}

__device__ __forceinline__ void mma8(float* d, const unsigned* a, unsigned b0, unsigned b1) {
    asm volatile(
        "mma.sync.aligned.m16n8k8.row.col.f32.tf32.tf32.f32 "
        "{%0,%1,%2,%3},{%4,%5,%6,%7},{%8,%9},{%0,%1,%2,%3};\n"
        : "+f"(d[0]), "+f"(d[1]), "+f"(d[2]), "+f"(d[3])
        : "r"(a[0]), "r"(a[1]), "r"(a[2]), "r"(a[3]), "r"(b0), "r"(b1));
}

// smem-A x gmem-B GEMM mainloop with register-double-buffered weight chunks.
// A: [128, KDIM] tf32 in smem (stride lda). B: W row-major [KDIM, NCOLS] fp32 in gmem.
// Warp computes a (MT*16) x (NT*8) tile at (warpRow, warpCol).
// Chunk = 16 K-rows staged through Bs; next chunk's LDGs issued before the
// current chunk's MMA block so L2/DRAM latency overlaps tensor work.
template <int KDIM, int NCOLS, int MT, int NT>
__device__ __forceinline__ void gemm_loop(
    const float* __restrict__ As, int lda, float* __restrict__ Bs,
    const float* __restrict__ W, float (&acc)[MT][NT][4],
    int warpRow, int warpCol, int tid, int gid, int tig)
{
    constexpr int R4 = (16 * NCOLS) / 1024;  // float4 per thread per chunk
    constexpr int C4 = NCOLS / 4;            // float4 per row
    float4 rb[R4];

    // prologue: chunk 0
#pragma unroll
    for (int i = 0; i < R4; i++) {
        int idx4 = tid + i * 256;
        int r = idx4 / C4, c = (idx4 % C4) * 4;
        rb[i] = *(const float4*)(W + (size_t)r * NCOLS + c);
    }

#pragma unroll 1
    for (int kc = 0; kc < KDIM; kc += 16) {
        __syncthreads();  // previous Bs chunk fully consumed / A ready on first iter
#pragma unroll
        for (int i = 0; i < R4; i++) {
            int idx4 = tid + i * 256;
            int r = idx4 / C4, c = (idx4 % C4) * 4;
            float4 v = rb[i];
            float4 t = make_float4(f2tf(v.x), f2tf(v.y), f2tf(v.z), f2tf(v.w));
            *(float4*)(Bs + r * LDB + c) = t;
        }
        __syncthreads();

        // prefetch next chunk — latency hidden behind the MMA block below
        if (kc + 16 < KDIM) {
#pragma unroll
            for (int i = 0; i < R4; i++) {
                int idx4 = tid + i * 256;
                int r = idx4 / C4, c = (idx4 % C4) * 4;
                rb[i] = *(const float4*)(W + (size_t)(kc + 16 + r) * NCOLS + c);
            }
        }

#pragma unroll
        for (int k8 = 0; k8 < 16; k8 += 8) {
            unsigned a[MT][4];
#pragma unroll
            for (int mt = 0; mt < MT; mt++) {
                const float* ap = As + (warpRow + mt * 16) * lda + kc + k8;
                a[mt][0] = __float_as_uint(ap[gid * lda + tig]);
                a[mt][1] = __float_as_uint(ap[(gid + 8) * lda + tig]);
                a[mt][2] = __float_as_uint(ap[gid * lda + tig + 4]);
                a[mt][3] = __float_as_uint(ap[(gid + 8) * lda + tig + 4]);
            }
#pragma unroll
            for (int nt = 0; nt < NT; nt++) {
                int col = warpCol + nt * 8 + gid;
                unsigned b0 = __float_as_uint(Bs[(k8 + tig) * LDB + col]);
                unsigned b1 = __float_as_uint(Bs[(k8 + tig + 4) * LDB + col]);
#pragma unroll
                for (int mt = 0; mt < MT; mt++) mma8(acc[mt][nt], a[mt], b0, b1);
            }
        }
    }
}

// Write accumulators (+bias) into H [128, 256] (stride LDH), raw fp32.
template <int MT, int NT>
__device__ __forceinline__ void store_acc_bias(
    float* __restrict__ H, const float (&acc)[MT][NT][4], const float* __restrict__ bias,
    int warpRow, int warpCol, int gid, int tig)
{
#pragma unroll
    for (int mt = 0; mt < MT; mt++) {
#pragma unroll
        for (int nt = 0; nt < NT; nt++) {
            int r0 = warpRow + mt * 16 + gid;
            int c0 = warpCol + nt * 8 + 2 * tig;
            H[r0 * LDH + c0]           = acc[mt][nt][0] + bias[c0];
            H[r0 * LDH + c0 + 1]       = acc[mt][nt][1] + bias[c0 + 1];
            H[(r0 + 8) * LDH + c0]     = acc[mt][nt][2] + bias[c0];
            H[(r0 + 8) * LDH + c0 + 1] = acc[mt][nt][3] + bias[c0 + 1];
        }
    }
}

// In-place LayerNorm+ReLU over 256-wide rows of H; writes back tf32.
__device__ __forceinline__ void ln_relu_256(
    float* __restrict__ H, const float* __restrict__ g, const float* __restrict__ b,
    int warp, int lane)
{
#pragma unroll 1
    for (int rr = 0; rr < 16; rr++) {
        int r = warp * 16 + rr;
        float v[8], s = 0.f, s2 = 0.f;
#pragma unroll
        for (int j = 0; j < 8; j++) {
            float x = H[r * LDH + lane + 32 * j];
            v[j] = x; s += x; s2 += x * x;
        }
#pragma unroll
        for (int o = 16; o; o >>= 1) {
            s  += __shfl_xor_sync(0xffffffffu, s, o);
            s2 += __shfl_xor_sync(0xffffffffu, s2, o);
        }
        float mu   = s * (1.f / 256.f);
        float var  = fmaf(-mu, mu, s2 * (1.f / 256.f));
        float rstd = rsqrtf(var + 1e-5f);
#pragma unroll
        for (int j = 0; j < 8; j++) {
            int c = lane + 32 * j;
            float y = fmaxf((v[j] - mu) * rstd * g[c] + b[c], 0.f);
            H[r * LDH + c] = f2tf(y);
        }
    }
}

}  // namespace

// batch may arrive as int32 or int64 (jax x64 ambiguity). If int64, the high
// 32-bit word of every element is 0 (values < 1024). Checking 32 hi-words == 0
// misidentifies int32 only with prob (1/1024)^32.
__global__ void detect_batch_kernel(const int* __restrict__ b32) {
    if (threadIdx.x == 0) {
        int ok = 1;
        for (int i = 0; i < 32; i++)
            if (b32[2 * i + 1] != 0) { ok = 0; break; }
        g_is64 = ok;
    }
}

__global__ void __launch_bounds__(256, 1)
fused_edge_kernel(const float* __restrict__ src, const float* __restrict__ dst_,
                  const float* __restrict__ ea, const float* __restrict__ u,
                  const void* __restrict__ batch_raw, const float* __restrict__ winding,
                  const float* __restrict__ Ww, const float* __restrict__ bw,
                  const float* __restrict__ gw, const float* __restrict__ betaw,
                  const float* __restrict__ W1, const float* __restrict__ b1,
                  const float* __restrict__ g1, const float* __restrict__ beta1,
                  const float* __restrict__ W2, const float* __restrict__ b2,
                  const float* __restrict__ g2, const float* __restrict__ beta2,
                  const float* __restrict__ W3, const float* __restrict__ b3,
                  float* __restrict__ out, int E)
{
    extern __shared__ float sm[];
    float* As = sm;                    // [128, LDA] x-tile, reused as h [128, LDH]
    float* Bs = sm + SM_A;             // [16, LDB] weight chunk
    float* P  = sm + SM_A + SM_B;      // params
    int* bsm  = (int*)(P + SM_P);      // batch ids [128]

    const int tid  = threadIdx.x;
    const int warp = tid >> 5, lane = tid & 31;
    const int gid  = lane >> 2, tig = lane & 3;
    const int e0   = blockIdx.x * 128;
    const int is64 = g_is64;

    // ---- stage params + batch ids ----
    if (tid < 256) {
        P[P_WW + tid]  = Ww[tid];
        P[P_B1 + tid]  = b1[tid];  P[P_G1 + tid]  = g1[tid];  P[P_BT1 + tid] = beta1[tid];
        P[P_B2 + tid]  = b2[tid];  P[P_G2 + tid]  = g2[tid];  P[P_BT2 + tid] = beta2[tid];
    }
    if (tid < 128) {
        P[P_BW + tid]  = bw[tid];  P[P_GW + tid]  = gw[tid];  P[P_BTW + tid] = betaw[tid];
        int e = e0 + tid;
        int b = 0;
        if (e < E)
            b = is64 ? (int)((const long long*)batch_raw)[e] : ((const int*)batch_raw)[e];
        bsm[tid] = b;
    }
    if (tid < 64) P[P_B3 + tid] = b3[tid];

    // ---- stage src/dest/edge_attr into A (cols 0..191), tf32, float4 loads ----
#pragma unroll 1
    for (int idx = tid; idx < 128 * 16; idx += 256) {
        int r = idx >> 4, c = (idx & 15) * 4;
        int e = e0 + r;
        float4 vs = make_float4(0.f, 0.f, 0.f, 0.f), vd = vs, ve = vs;
        if (e < E) {
            size_t o = (size_t)e * 64 + c;
            vs = *(const float4*)(src + o);
            vd = *(const float4*)(dst_ + o);
            ve = *(const float4*)(ea + o);
        }
        *(float4*)(As + r * LDA + c) =
            make_float4(f2tf(vs.x), f2tf(vs.y), f2tf(vs.z), f2tf(vs.w));
        *(float4*)(As + r * LDA + 64 + c) =
            make_float4(f2tf(vd.x), f2tf(vd.y), f2tf(vd.z), f2tf(vd.w));
        *(float4*)(As + r * LDA + 128 + c) =
            make_float4(f2tf(ve.x), f2tf(ve.y), f2tf(ve.z), f2tf(ve.w));
    }
    __syncthreads();  // bsm + P ready

    // ---- gather u[batch] into A (cols 192..255), float4 ----
#pragma unroll 1
    for (int idx = tid; idx < 128 * 16; idx += 256) {
        int r = idx >> 4, c = (idx & 15) * 4;
        float4 v = make_float4(0.f, 0.f, 0.f, 0.f);
        if (e0 + r < E) v = *(const float4*)(u + (size_t)bsm[r] * 64 + c);
        *(float4*)(As + r * LDA + 192 + c) =
            make_float4(f2tf(v.x), f2tf(v.y), f2tf(v.z), f2tf(v.w));
    }

    // ---- winding MLP -> A (cols 256..383): Linear(2->128) + LN + ReLU ----
#pragma unroll 1
    for (int rr = 0; rr < 16; rr++) {
        int r = warp * 16 + rr;
        int e = e0 + r;
        float w0 = 0.f, w1 = 0.f;
        if (e < E) { w0 = winding[(size_t)e * 2]; w1 = winding[(size_t)e * 2 + 1]; }
        float v[4], s = 0.f, s2 = 0.f;
#pragma unroll
        for (int j = 0; j < 4; j++) {
            int c = lane * 4 + j;
            float x = fmaf(w0, P[P_WW + c], fmaf(w1, P[P_WW + 128 + c], P[P_BW + c]));
            v[j] = x; s += x; s2 += x * x;
        }
#pragma unroll
        for (int o = 16; o; o >>= 1) {
            s  += __shfl_xor_sync(0xffffffffu, s, o);
            s2 += __shfl_xor_sync(0xffffffffu, s2, o);
        }
        float mu   = s * (1.f / 128.f);
        float var  = fmaf(-mu, mu, s2 * (1.f / 128.f));
        float rstd = rsqrtf(var + 1e-5f);
#pragma unroll
        for (int j = 0; j < 4; j++) {
            int c = lane * 4 + j;
            float y = fmaxf((v[j] - mu) * rstd * P[P_GW + c] + P[P_BTW + c], 0.f);
            if (e >= E) y = 0.f;
            As[r * LDA + 256 + c] = f2tf(y);
        }
    }
    // gemm_loop starts with __syncthreads() -> A fully visible

    const int wR = (warp >> 2) * 64;
    const int wC = (warp & 3) * 64;

    // ---- GEMM1: [128,384] x [384,256] ----
    float acc[4][8][4];
#pragma unroll
    for (int mt = 0; mt < 4; mt++)
#pragma unroll
        for (int nt = 0; nt < 8; nt++)
#pragma unroll
            for (int j = 0; j < 4; j++) acc[mt][nt][j] = 0.f;
    gemm_loop<384, 256, 4, 8>(As, LDA, Bs, W1, acc, wR, wC, tid, gid, tig);

    __syncthreads();
    store_acc_bias<4, 8>(As, acc, P + P_B1, wR, wC, gid, tig);
    __syncthreads();
    ln_relu_256(As, P + P_G1, P + P_BT1, warp, lane);

    // ---- GEMM2: [128,256] x [256,256] ----
#pragma unroll
    for (int mt = 0; mt < 4; mt++)
#pragma unroll
        for (int nt = 0; nt < 8; nt++)
#pragma unroll
            for (int j = 0; j < 4; j++) acc[mt][nt][j] = 0.f;
    gemm_loop<256, 256, 4, 8>(As, LDH, Bs, W2, acc, wR, wC, tid, gid, tig);

    __syncthreads();
    store_acc_bias<4, 8>(As, acc, P + P_B2, wR, wC, gid, tig);
    __syncthreads();
    ln_relu_256(As, P + P_G2, P + P_BT2, warp, lane);

    // ---- GEMM3: [128,256] x [256,64] ----
    float acc3[2][4][4];
#pragma unroll
    for (int mt = 0; mt < 2; mt++)
#pragma unroll
        for (int nt = 0; nt < 4; nt++)
#pragma unroll
            for (int j = 0; j < 4; j++) acc3[mt][nt][j] = 0.f;
    const int wR3 = (warp >> 1) * 32;
    const int wC3 = (warp & 1) * 32;
    gemm_loop<256, 64, 2, 4>(As, LDH, Bs, W3, acc3, wR3, wC3, tid, gid, tig);

    // ---- epilogue: + b3, store ----
#pragma unroll
    for (int mt = 0; mt < 2; mt++) {
#pragma unroll
        for (int nt = 0; nt < 4; nt++) {
            int r0 = wR3 + mt * 16 + gid;
            int c0 = wC3 + nt * 8 + 2 * tig;
            int e  = e0 + r0;
            if (e < E) {
                float2 v = make_float2(acc3[mt][nt][0] + P[P_B3 + c0],
                                       acc3[mt][nt][1] + P[P_B3 + c0 + 1]);
                *(float2*)(out + (size_t)e * 64 + c0) = v;
            }
            e = e0 + r0 + 8;
            if (e < E) {
                float2 v = make_float2(acc3[mt][nt][2] + P[P_B3 + c0],
                                       acc3[mt][nt][3] + P[P_B3 + c0 + 1]);
                *(float2*)(out + (size_t)e * 64 + c0) = v;
            }
        }
    }
}

extern "C" void kernel_launch(void* const* d_in, const int* in_sizes, int n_in,
                              void* d_out, int out_size)
{
    const float* src     = (const float*)d_in[0];
    const float* dst_    = (const float*)d_in[1];
    const float* ea      = (const float*)d_in[2];
    const float* u       = (const float*)d_in[3];
    const void*  batch   = d_in[4];
    const float* winding = (const float*)d_in[5];
    const float* Ww      = (const float*)d_in[6];
    const float* bw      = (const float*)d_in[7];
    const float* gw      = (const float*)d_in[8];
    const float* betaw   = (const float*)d_in[9];
    const float* W1      = (const float*)d_in[10];
    const float* b1      = (const float*)d_in[11];
    const float* g1      = (const float*)d_in[12];
    const float* beta1   = (const float*)d_in[13];
    const float* W2      = (const float*)d_in[14];
    const float* b2      = (const float*)d_in[15];
    const float* g2      = (const float*)d_in[16];
    const float* beta2   = (const float*)d_in[17];
    const float* W3      = (const float*)d_in[18];
    const float* b3      = (const float*)d_in[19];

    const int E = in_sizes[0] / 64;

    cudaFuncSetAttribute(fused_edge_kernel,
                         cudaFuncAttributeMaxDynamicSharedMemorySize, SMEM_BYTES);

    detect_batch_kernel<<<1, 32>>>((const int*)batch);

    const int grid = (E + 127) / 128;
    fused_edge_kernel<<<grid, 256, SMEM_BYTES>>>(
        src, dst_, ea, u, batch, winding,
        Ww, bw, gw, betaw,
        W1, b1, g1, beta1,
        W2, b2, g2, beta2,
        W3, b3,
        (float*)d_out, E);
}

// round 5
// speedup vs baseline: 1.6861x; 1.1963x over previous
#include <cuda_runtime.h>
#include <cstdint>

namespace {

constexpr int ROWS = 64;               // edges per CTA
constexpr int LDA = 260;               // A/h stride (256+4): conflict-free frags
constexpr int LDB = 264;               // B stride (256+8): conflict-free frags
constexpr int A_OFF = 0;               // 64*260 = 16640 floats
constexpr int B_OFF = 16640;           // 2 bufs x 16*264 = 8448 floats
constexpr int P_OFF = 25088;           // 2240 params
constexpr int BSM_OFF = 27328;         // 64 batch ids
constexpr int SMF = 27392;
constexpr int SMEM_BYTES = SMF * 4;    // 109568 B -> 2 CTAs/SM

constexpr int Pb1 = 0, Pg1 = 256, Pt1 = 512, Pb2 = 768, Pg2 = 1024, Pt2 = 1280;
constexpr int Pb3 = 1536, PWw = 1600, Pbw = 1856, Pgw = 1984, Ptw = 2112;

// tf32-pre-rounded weights, original row-major layout
constexpr int W2B = 98304, W3B = 163840;
__device__ float g_wt[180224];
__device__ int g_is64;

__device__ __forceinline__ float f2tf(float f) {
    unsigned u; asm("cvt.rna.tf32.f32 %0, %1;" : "=r"(u) : "f"(f));
    return __uint_as_float(u);
}
__device__ __forceinline__ uint32_t smem_u32(const void* p) {
    uint32_t a;
    asm("{ .reg .u64 t; cvta.to.shared.u64 t, %1; cvt.u32.u64 %0, t; }" : "=r"(a) : "l"(p));
    return a;
}
__device__ __forceinline__ void mma8(float* d, const unsigned* a, unsigned b0, unsigned b1) {
    asm volatile(
        "mma.sync.aligned.m16n8k8.row.col.f32.tf32.tf32.f32 "
        "{%0,%1,%2,%3},{%4,%5,%6,%7},{%8,%9},{%0,%1,%2,%3};\n"
        : "+f"(d[0]), "+f"(d[1]), "+f"(d[2]), "+f"(d[3])
        : "r"(a[0]), "r"(a[1]), "r"(a[2]), "r"(a[3]), "r"(b0), "r"(b1));
}

// async-copy one 16-row weight chunk (NCOLS wide) into Bb (stride LDB)
template <int NCOLS>
__device__ __forceinline__ void stage_chunk(const float* __restrict__ Wc,
                                            float* __restrict__ Bb, int tid) {
    constexpr int OPS = (16 * NCOLS) / 1024;   // float4 per thread
    const uint32_t s = smem_u32(Bb);
#pragma unroll
    for (int i = 0; i < OPS; i++) {
        int idx4 = tid + i * 256;
        int r = idx4 / (NCOLS / 4), c = (idx4 % (NCOLS / 4)) * 4;
        uint32_t dst = s + (uint32_t)(r * LDB + c) * 4;
        const float* srcp = Wc + (size_t)r * NCOLS + c;
        asm volatile("cp.async.cg.shared.global [%0], [%1], 16;\n"
                     :: "r"(dst), "l"(srcp));
    }
}

// GEMM mainloop: A [64,K] tf32 in smem (LDA), W tf32 gmem row-major [K,NCOLS],
// double-buffered cp.async chunks, 1 syncthreads per 16-K chunk.
// Warp tile (MT*16) x (NT*8) at (wR, wC). acc persists (caller zeroes).
template <int NCOLS, int MT, int NT>
__device__ __forceinline__ void gemm_ca(
    const float* __restrict__ W, int nchunks,
    const float* __restrict__ As, float* __restrict__ Bs,
    float (&acc)[MT][NT][4], int wR, int wC, int tid, int gid, int tig)
{
    stage_chunk<NCOLS>(W, Bs, tid);
    asm volatile("cp.async.commit_group;\n");
#pragma unroll 1
    for (int c = 0; c < nchunks; c++) {
        asm volatile("cp.async.wait_group 0;\n" ::: "memory");
        __syncthreads();   // chunk c visible; also publishes prior A writes
        if (c + 1 < nchunks) {
            stage_chunk<NCOLS>(W + (size_t)(c + 1) * 16 * NCOLS,
                               Bs + ((c + 1) & 1) * (16 * LDB), tid);
            asm volatile("cp.async.commit_group;\n");
        }
        const float* B = Bs + (c & 1) * (16 * LDB);
        const int kc = c * 16;
#pragma unroll
        for (int k8 = 0; k8 < 16; k8 += 8) {
            unsigned a[MT][4];
#pragma unroll
            for (int mt = 0; mt < MT; mt++) {
                const float* ap = As + (wR + mt * 16) * LDA + kc + k8;
                a[mt][0] = __float_as_uint(ap[gid * LDA + tig]);
                a[mt][1] = __float_as_uint(ap[(gid + 8) * LDA + tig]);
                a[mt][2] = __float_as_uint(ap[gid * LDA + tig + 4]);
                a[mt][3] = __float_as_uint(ap[(gid + 8) * LDA + tig + 4]);
            }
#pragma unroll
            for (int nt = 0; nt < NT; nt++) {
                int col = wC + nt * 8 + gid;
                unsigned b0 = __float_as_uint(B[(k8 + tig) * LDB + col]);
                unsigned b1 = __float_as_uint(B[(k8 + tig + 4) * LDB + col]);
#pragma unroll
                for (int mt = 0; mt < MT; mt++) mma8(acc[mt][nt], a[mt], b0, b1);
            }
        }
    }
}

// acc(+bias) -> H [64,256] stride LDA (raw fp32)
template <int MT, int NT>
__device__ __forceinline__ void store_acc_bias(
    float* __restrict__ H, const float (&acc)[MT][NT][4], const float* __restrict__ bias,
    int wR, int wC, int gid, int tig)
{
#pragma unroll
    for (int mt = 0; mt < MT; mt++)
#pragma unroll
        for (int nt = 0; nt < NT; nt++) {
            int r0 = wR + mt * 16 + gid;
            int c0 = wC + nt * 8 + 2 * tig;
            H[r0 * LDA + c0]           = acc[mt][nt][0] + bias[c0];
            H[r0 * LDA + c0 + 1]       = acc[mt][nt][1] + bias[c0 + 1];
            H[(r0 + 8) * LDA + c0]     = acc[mt][nt][2] + bias[c0];
            H[(r0 + 8) * LDA + c0 + 1] = acc[mt][nt][3] + bias[c0 + 1];
        }
}

// in-place LN+ReLU over 256-wide rows of H (64 rows, 8/warp), writes tf32
__device__ __forceinline__ void ln_relu(
    float* __restrict__ H, const float* __restrict__ g, const float* __restrict__ b,
    int warp, int lane)
{
#pragma unroll 1
    for (int rr = 0; rr < 8; rr++) {
        int r = warp * 8 + rr;
        float v[8], s = 0.f, q = 0.f;
#pragma unroll
        for (int j = 0; j < 8; j++) {
            float x = H[r * LDA + lane + 32 * j];
            v[j] = x; s += x; q += x * x;
        }
#pragma unroll
        for (int o = 16; o; o >>= 1) {
            s += __shfl_xor_sync(~0u, s, o);
            q += __shfl_xor_sync(~0u, q, o);
        }
        float mu = s * (1.f / 256.f);
        float var = fmaf(-mu, mu, q * (1.f / 256.f));
        float rs = rsqrtf(var + 1e-5f);
#pragma unroll
        for (int j = 0; j < 8; j++) {
            int c = lane + 32 * j;
            H[r * LDA + c] = f2tf(fmaxf(fmaf((v[j] - mu) * rs, g[c], b[c]), 0.f));
        }
    }
}

}  // namespace

__global__ void detect_batch_kernel(const int* __restrict__ b32) {
    if (threadIdx.x == 0) {
        int ok = 1;
        for (int i = 0; i < 32; i++)
            if (b32[2 * i + 1] != 0) { ok = 0; break; }
        g_is64 = ok;
    }
}

__global__ void prep_weights(const float* __restrict__ W1, const float* __restrict__ W2,
                             const float* __restrict__ W3) {
    int id = blockIdx.x * 256 + threadIdx.x;
    if (id < W2B)            g_wt[id] = f2tf(W1[id]);
    else if (id < W3B)       g_wt[id] = f2tf(W2[id - W2B]);
    else if (id < 180224)    g_wt[id] = f2tf(W3[id - W3B]);
}

__global__ void __launch_bounds__(256, 2)
fused_edge_kernel(const float* __restrict__ src, const float* __restrict__ dst_,
                  const float* __restrict__ ea, const float* __restrict__ u,
                  const void* __restrict__ braw, const float* __restrict__ wind,
                  const float* __restrict__ bw, const float* __restrict__ gw,
                  const float* __restrict__ btw, const float* __restrict__ Ww,
                  const float* __restrict__ b1, const float* __restrict__ g1,
                  const float* __restrict__ bt1, const float* __restrict__ b2,
                  const float* __restrict__ g2, const float* __restrict__ bt2,
                  const float* __restrict__ b3, float* __restrict__ out, int E)
{
    extern __shared__ float sm[];
    float* As = sm + A_OFF;
    float* Bs = sm + B_OFF;
    float* P  = sm + P_OFF;
    int* bsm  = (int*)(sm + BSM_OFF);

    const int tid = threadIdx.x;
    const int warp = tid >> 5, lane = tid & 31;
    const int gid = lane >> 2, tig = lane & 3;
    const int e0 = blockIdx.x * ROWS;
    const int is64 = g_is64;

    // params + batch ids
    if (tid < 256) {
        P[PWw + tid] = Ww[tid];
        P[Pb1 + tid] = b1[tid]; P[Pg1 + tid] = g1[tid]; P[Pt1 + tid] = bt1[tid];
        P[Pb2 + tid] = b2[tid]; P[Pg2 + tid] = g2[tid]; P[Pt2 + tid] = bt2[tid];
        if (tid < 128) { P[Pbw + tid] = bw[tid]; P[Pgw + tid] = gw[tid]; P[Ptw + tid] = btw[tid]; }
        if (tid < 64) {
            P[Pb3 + tid] = b3[tid];
            int e = e0 + tid;
            bsm[tid] = (e < E) ? (is64 ? (int)((const long long*)braw)[e]
                                       : ((const int*)braw)[e]) : 0;
        }
    }
    __syncthreads();

    // stage x pass-1 cols: src|dest|ea|u[batch] -> A cols 0..255 (tf32)
#pragma unroll 1
    for (int idx = tid; idx < ROWS * 16; idx += 256) {
        int r = idx >> 4, c = (idx & 15) * 4;
        int e = e0 + r;
        float4 a = {0,0,0,0}, b = a, cc = a, d = a;
        if (e < E) {
            size_t o = (size_t)e * 64 + c;
            a = *(const float4*)(src + o);
            b = *(const float4*)(dst_ + o);
            cc = *(const float4*)(ea + o);
        }
        d = *(const float4*)(u + (size_t)bsm[r] * 64 + c);
        *(float4*)(As + r * LDA + c)       = make_float4(f2tf(a.x), f2tf(a.y), f2tf(a.z), f2tf(a.w));
        *(float4*)(As + r * LDA + 64 + c)  = make_float4(f2tf(b.x), f2tf(b.y), f2tf(b.z), f2tf(b.w));
        *(float4*)(As + r * LDA + 128 + c) = make_float4(f2tf(cc.x), f2tf(cc.y), f2tf(cc.z), f2tf(cc.w));
        *(float4*)(As + r * LDA + 192 + c) = make_float4(f2tf(d.x), f2tf(d.y), f2tf(d.z), f2tf(d.w));
    }
    // (gemm_ca's first wait+sync publishes A)

    const int wR = (warp >> 2) * 32;       // {0,32}
    const int wC = (warp & 3) * 64;        // {0,64,128,192}

    float acc[2][8][4];
#pragma unroll
    for (int mt = 0; mt < 2; mt++)
#pragma unroll
        for (int nt = 0; nt < 8; nt++)
#pragma unroll
            for (int j = 0; j < 4; j++) acc[mt][nt][j] = 0.f;

    // GEMM1 pass 1: x[:,0:256] @ W1[0:256,:]
    gemm_ca<256, 2, 8>(g_wt, 16, As, Bs, acc, wR, wC, tid, gid, tig);

    __syncthreads();  // pass-1 frag reads done before overwriting A cols 0..127

    // winding MLP -> A cols 0..127 (tf32): Linear(2->128)+LN+ReLU
#pragma unroll 1
    for (int rr = 0; rr < 8; rr++) {
        int r = warp * 8 + rr, e = e0 + r;
        float w0 = 0.f, w1 = 0.f;
        if (e < E) { w0 = wind[(size_t)e * 2]; w1 = wind[(size_t)e * 2 + 1]; }
        float v[4], s = 0.f, q = 0.f;
#pragma unroll
        for (int j = 0; j < 4; j++) {
            int c = lane * 4 + j;
            float x = fmaf(w0, P[PWw + c], fmaf(w1, P[PWw + 128 + c], P[Pbw + c]));
            v[j] = x; s += x; q += x * x;
        }
#pragma unroll
        for (int o = 16; o; o >>= 1) {
            s += __shfl_xor_sync(~0u, s, o);
            q += __shfl_xor_sync(~0u, q, o);
        }
        float mu = s * (1.f / 128.f);
        float var = fmaf(-mu, mu, q * (1.f / 128.f));
        float rs = rsqrtf(var + 1e-5f);
#pragma unroll
        for (int j = 0; j < 4; j++) {
            int c = lane * 4 + j;
            As[r * LDA + c] = f2tf(fmaxf(fmaf((v[j] - mu) * rs, P[Pgw + c], P[Ptw + c]), 0.f));
        }
    }

    // GEMM1 pass 2: w @ W1[256:384,:] (accumulate into acc)
    gemm_ca<256, 2, 8>(g_wt + 256 * 256, 8, As, Bs, acc, wR, wC, tid, gid, tig);

    __syncthreads();
    store_acc_bias<2, 8>(As, acc, P + Pb1, wR, wC, gid, tig);
    __syncthreads();
    ln_relu(As, P + Pg1, P + Pt1, warp, lane);

    // GEMM2: h1 @ W2
#pragma unroll
    for (int mt = 0; mt < 2; mt++)
#pragma unroll
        for (int nt = 0; nt < 8; nt++)
#pragma unroll
            for (int j = 0; j < 4; j++) acc[mt][nt][j] = 0.f;
    gemm_ca<256, 2, 8>(g_wt + W2B, 16, As, Bs, acc, wR, wC, tid, gid, tig);

    __syncthreads();
    store_acc_bias<2, 8>(As, acc, P + Pb2, wR, wC, gid, tig);
    __syncthreads();
    ln_relu(As, P + Pg2, P + Pt2, warp, lane);

    // GEMM3: h2 @ W3 (N=64)
    float acc3[2][2][4];
#pragma unroll
    for (int mt = 0; mt < 2; mt++)
#pragma unroll
        for (int nt = 0; nt < 2; nt++)
#pragma unroll
            for (int j = 0; j < 4; j++) acc3[mt][nt][j] = 0.f;
    const int wR3 = (warp >> 2) * 32;
    const int wC3 = (warp & 3) * 16;
    gemm_ca<64, 2, 2>(g_wt + W3B, 16, As, Bs, acc3, wR3, wC3, tid, gid, tig);

    // epilogue: +b3, store
#pragma unroll
    for (int mt = 0; mt < 2; mt++)
#pragma unroll
        for (int nt = 0; nt < 2; nt++) {
            int r0 = wR3 + mt * 16 + gid;
            int c0 = wC3 + nt * 8 + 2 * tig;
            int e = e0 + r0;
            if (e < E)
                *(float2*)(out + (size_t)e * 64 + c0) =
                    make_float2(acc3[mt][nt][0] + P[Pb3 + c0],
                                acc3[mt][nt][1] + P[Pb3 + c0 + 1]);
            e = e0 + r0 + 8;
            if (e < E)
                *(float2*)(out + (size_t)e * 64 + c0) =
                    make_float2(acc3[mt][nt][2] + P[Pb3 + c0],
                                acc3[mt][nt][3] + P[Pb3 + c0 + 1]);
        }
}

extern "C" void kernel_launch(void* const* d_in, const int* in_sizes, int n_in,
                              void* d_out, int out_size)
{
    const float* src = (const float*)d_in[0];
    const float* dst_ = (const float*)d_in[1];
    const float* ea = (const float*)d_in[2];
    const float* u = (const float*)d_in[3];
    const void* batch = d_in[4];
    const float* wind = (const float*)d_in[5];
    const float* Ww = (const float*)d_in[6];
    const float* bw = (const float*)d_in[7];
    const float* gw = (const float*)d_in[8];
    const float* btw = (const float*)d_in[9];
    const float* W1 = (const float*)d_in[10];
    const float* b1 = (const float*)d_in[11];
    const float* g1 = (const float*)d_in[12];
    const float* bt1 = (const float*)d_in[13];
    const float* W2 = (const float*)d_in[14];
    const float* b2 = (const float*)d_in[15];
    const float* g2 = (const float*)d_in[16];
    const float* bt2 = (const float*)d_in[17];
    const float* W3 = (const float*)d_in[18];
    const float* b3 = (const float*)d_in[19];
    const int E = in_sizes[0] / 64;

    cudaFuncSetAttribute(fused_edge_kernel,
                         cudaFuncAttributeMaxDynamicSharedMemorySize, SMEM_BYTES);

    detect_batch_kernel<<<1, 32>>>((const int*)batch);
    prep_weights<<<704, 256>>>(W1, W2, W3);

    fused_edge_kernel<<<(E + ROWS - 1) / ROWS, 256, SMEM_BYTES>>>(
        src, dst_, ea, u, batch, wind,
        bw, gw, btw, Ww,
        b1, g1, bt1, b2, g2, bt2, b3, (float*)d_out, E);
}

// round 6
// speedup vs baseline: 1.7172x; 1.0184x over previous
#include <cuda_runtime.h>
#include <cstdint>

namespace {

constexpr int ROWS = 64;           // edges per CTA
constexpr int BLKW = 132;          // words per A frag block (512B + 16B pad)
constexpr int A_OFF = 0;           // 4 mb x 32 kb blocks = 128*132 = 16896 floats
constexpr int B_OFF = 16896;       // 2 x 4096-float chunk buffers
constexpr int P_OFF = 25088;       // 2240 params
constexpr int BSM_OFF = 27328;     // 64 batch ids
constexpr int SMF = 27392;
constexpr int SMEM_BYTES = SMF * 4;   // 109568 B -> 2 CTAs/SM

constexpr int Pb1 = 0, Pg1 = 256, Pt1 = 512, Pb2 = 768, Pg2 = 1024, Pt2 = 1280;
constexpr int Pb3 = 1536, PWw = 1600, Pbw = 1856, Pgw = 1984, Ptw = 2112;

constexpr int W2B = 98304, W3B = 163840;
__device__ float g_wt[180224];
__device__ int g_is64;

__device__ __forceinline__ float f2tf(float f) {
    unsigned u; asm("cvt.rna.tf32.f32 %0, %1;" : "=r"(u) : "f"(f));
    return __uint_as_float(u);
}
__device__ __forceinline__ uint32_t smem_u32(const void* p) {
    uint32_t a;
    asm("{ .reg .u64 t; cvta.to.shared.u64 t, %1; cvt.u32.u64 %0, t; }" : "=r"(a) : "l"(p));
    return a;
}
__device__ __forceinline__ void mma8(float* d, const unsigned* a, unsigned b0, unsigned b1) {
    asm volatile(
        "mma.sync.aligned.m16n8k8.row.col.f32.tf32.tf32.f32 "
        "{%0,%1,%2,%3},{%4,%5,%6,%7},{%8,%9},{%0,%1,%2,%3};\n"
        : "+f"(d[0]), "+f"(d[1]), "+f"(d[2]), "+f"(d[3])
        : "r"(a[0]), "r"(a[1]), "r"(a[2]), "r"(a[3]), "r"(b0), "r"(b1));
}
__device__ __forceinline__ int a_word(int mb, int kb) { return (mb * 32 + kb) * BLKW; }

// GEMM mainloop over frag-packed operands; double-buffered cp.async weight chunks.
template <int CHUNKF, int MT, int NT>
__device__ __forceinline__ void gemm_ca(
    const float* __restrict__ W, int nchunks,
    const float* __restrict__ As, float* __restrict__ Bs,
    float (&acc)[MT][NT][4], int mb0, int nb0, int tid, int lane)
{
    constexpr int OPS = CHUNKF / 1024;
    {
        const uint32_t s = smem_u32(Bs);
#pragma unroll
        for (int i = 0; i < OPS; i++) {
            int i4 = tid + i * 256;
            asm volatile("cp.async.cg.shared.global [%0], [%1], 16;\n"
                         :: "r"(s + i4 * 16), "l"(W + i4 * 4));
        }
        asm volatile("cp.async.commit_group;\n");
    }
#pragma unroll 1
    for (int c = 0; c < nchunks; c++) {
        asm volatile("cp.async.wait_group 0;\n" ::: "memory");
        __syncthreads();
        if (c + 1 < nchunks) {
            const uint32_t s = smem_u32(Bs + ((c + 1) & 1) * CHUNKF);
            const float* Wn = W + (size_t)(c + 1) * CHUNKF;
#pragma unroll
            for (int i = 0; i < OPS; i++) {
                int i4 = tid + i * 256;
                asm volatile("cp.async.cg.shared.global [%0], [%1], 16;\n"
                             :: "r"(s + i4 * 16), "l"(Wn + i4 * 4));
            }
            asm volatile("cp.async.commit_group;\n");
        }
        const float* B = Bs + (c & 1) * CHUNKF;
#pragma unroll
        for (int k81 = 0; k81 < 2; k81++) {
            const int kb = c * 2 + k81;
            unsigned a[MT][4];
#pragma unroll
            for (int mt = 0; mt < MT; mt++) {
                float4 av = *(const float4*)(As + a_word(mb0 + mt, kb) + lane * 4);
                a[mt][0] = __float_as_uint(av.x); a[mt][1] = __float_as_uint(av.y);
                a[mt][2] = __float_as_uint(av.z); a[mt][3] = __float_as_uint(av.w);
            }
            const float* Bk = B + k81 * (CHUNKF / 2);
#pragma unroll
            for (int nt = 0; nt < NT; nt++) {
                float2 bv = *(const float2*)(Bk + (nb0 + nt) * 64 + lane * 2);
                unsigned b0 = __float_as_uint(bv.x), b1 = __float_as_uint(bv.y);
#pragma unroll
                for (int mt = 0; mt < MT; mt++) mma8(acc[mt][nt], a[mt], b0, b1);
            }
        }
    }
}

template <int MT, int NT>
__device__ __forceinline__ void store_acc_frag(
    float* __restrict__ A, const float (&acc)[MT][NT][4], const float* __restrict__ bias,
    int mb0, int nb0, int gid, int tig)
{
    const int base = gid * 16 + ((tig & 1) * 2) * 4 + 2 * (tig >> 1);
#pragma unroll
    for (int mt = 0; mt < MT; mt++)
#pragma unroll
        for (int nt = 0; nt < NT; nt++) {
            int c0 = (nb0 + nt) * 8 + 2 * tig;
            int w = a_word(mb0 + mt, nb0 + nt) + base;
            A[w]     = acc[mt][nt][0] + bias[c0];
            A[w + 4] = acc[mt][nt][1] + bias[c0 + 1];
            A[w + 1] = acc[mt][nt][2] + bias[c0];
            A[w + 5] = acc[mt][nt][3] + bias[c0 + 1];
        }
}

__device__ __forceinline__ void ln_relu_frag(
    float* __restrict__ A, const float* __restrict__ g, const float* __restrict__ b,
    int warp, int lane)
{
    const int mb = warp >> 1, hir = warp & 1;
    const int off = (lane & 3) * 4 + hir + 2 * ((lane >> 2) & 1);
    const int kbl = lane >> 3;
#pragma unroll 1
    for (int rr = 0; rr < 8; rr++) {
        const int wb = rr * 16 + off;
        float v[8], s = 0.f, q = 0.f;
#pragma unroll
        for (int j = 0; j < 8; j++) {
            float x = A[a_word(mb, kbl + 4 * j) + wb];
            v[j] = x; s += x; q += x * x;
        }
#pragma unroll
        for (int o = 16; o; o >>= 1) {
            s += __shfl_xor_sync(~0u, s, o);
            q += __shfl_xor_sync(~0u, q, o);
        }
        float mu = s * (1.f / 256.f);
        float var = fmaf(-mu, mu, q * (1.f / 256.f));
        float rs = rsqrtf(var + 1e-5f);
#pragma unroll
        for (int j = 0; j < 8; j++) {
            int c = lane + 32 * j;
            A[a_word(mb, kbl + 4 * j) + wb] =
                f2tf(fmaxf(fmaf((v[j] - mu) * rs, g[c], b[c]), 0.f));
        }
    }
}

}  // namespace

__global__ void detect_batch_kernel(const int* __restrict__ b32) {
    int bad = (b32[2 * threadIdx.x + 1] != 0);
    unsigned m = __ballot_sync(~0u, bad);
    if (threadIdx.x == 0) g_is64 = (m == 0);
}

__global__ void prep_weights(const float* __restrict__ W1, const float* __restrict__ W2,
                             const float* __restrict__ W3) {
    int id = blockIdx.x * 256 + threadIdx.x;
    if (id >= 180224) return;
    const float* W; int t, cf, ncols, base;
    if (id < W2B)      { W = W1; t = id;        cf = 4096; ncols = 256; base = 0;   }
    else if (id < W3B) { W = W2; t = id - W2B;  cf = 4096; ncols = 256; base = W2B; }
    else               { W = W3; t = id - W3B;  cf = 1024; ncols = 64;  base = W3B; }
    int c = t / cf, rem = t % cf;
    int k81 = rem / (cf / 2), rem2 = rem % (cf / 2);
    int nb = rem2 / 64, l = (rem2 % 64) / 2, pair = rem2 & 1;
    int k = (c * 2 + k81) * 8 + (l & 3) + pair * 4;
    int n = nb * 8 + (l >> 2);
    g_wt[base + t] = f2tf(W[k * ncols + n]);
}

__global__ void __launch_bounds__(256, 2)
fused_edge_kernel(const float* __restrict__ src, const float* __restrict__ dst_,
                  const float* __restrict__ ea, const float* __restrict__ u,
                  const void* __restrict__ braw, const float* __restrict__ wind,
                  const float* __restrict__ bw, const float* __restrict__ gw,
                  const float* __restrict__ btw, const float* __restrict__ Ww,
                  const float* __restrict__ b1, const float* __restrict__ g1,
                  const float* __restrict__ bt1, const float* __restrict__ b2,
                  const float* __restrict__ g2, const float* __restrict__ bt2,
                  const float* __restrict__ b3, float* __restrict__ out, int E)
{
    extern __shared__ float sm[];
    float* As = sm + A_OFF;
    float* Bs = sm + B_OFF;
    float* P  = sm + P_OFF;
    int* bsm  = (int*)(sm + BSM_OFF);

    const int tid = threadIdx.x;
    const int warp = tid >> 5, lane = tid & 31;
    const int gid = lane >> 2, tig = lane & 3;
    const int e0 = blockIdx.x * ROWS;
    const int is64 = g_is64;

    if (tid < 256) {
        P[PWw + tid] = Ww[tid];
        P[Pb1 + tid] = b1[tid]; P[Pg1 + tid] = g1[tid]; P[Pt1 + tid] = bt1[tid];
        P[Pb2 + tid] = b2[tid]; P[Pg2 + tid] = g2[tid]; P[Pt2 + tid] = bt2[tid];
        if (tid < 128) { P[Pbw + tid] = bw[tid]; P[Pgw + tid] = gw[tid]; P[Ptw + tid] = btw[tid]; }
        if (tid < 64) {
            P[Pb3 + tid] = b3[tid];
            int e = e0 + tid;
            bsm[tid] = (e < E) ? (is64 ? (int)((const long long*)braw)[e]
                                       : ((const int*)braw)[e]) : 0;
        }
    }
    __syncthreads();

    // stage x: src|dest|ea|u[batch] -> frag-packed A cols 0..255 (tf32)
#pragma unroll 1
    for (int idx = tid; idx < ROWS * 16; idx += 256) {
        int r = idx >> 4, c4 = (idx & 15) * 4;
        int e = e0 + r;
        float4 vv[4];
        vv[0] = vv[1] = vv[2] = vv[3] = make_float4(0.f, 0.f, 0.f, 0.f);
        if (e < E) {
            size_t o = (size_t)e * 64 + c4;
            vv[0] = *(const float4*)(src + o);
            vv[1] = *(const float4*)(dst_ + o);
            vv[2] = *(const float4*)(ea + o);
        }
        vv[3] = *(const float4*)(u + (size_t)bsm[r] * 64 + c4);
        const int mb = r >> 4, gd = r & 7, hir = (r >> 3) & 1;
        const int hic = (c4 >> 2) & 1, kbq = c4 >> 3;
        const int wb = gd * 16 + hir + 2 * hic;
#pragma unroll
        for (int reg = 0; reg < 4; reg++) {
            int w = a_word(mb, reg * 8 + kbq) + wb;
            const float* vp = &vv[reg].x;
            As[w]      = f2tf(vp[0]);
            As[w + 4]  = f2tf(vp[1]);
            As[w + 8]  = f2tf(vp[2]);
            As[w + 12] = f2tf(vp[3]);
        }
    }

    const int mb0 = (warp >> 2) * 2;
    const int nb0 = (warp & 3) * 8;

    float acc[2][8][4];
#pragma unroll
    for (int mt = 0; mt < 2; mt++)
#pragma unroll
        for (int nt = 0; nt < 8; nt++)
#pragma unroll
            for (int j = 0; j < 4; j++) acc[mt][nt][j] = 0.f;

    // GEMM1 pass 1: x[:,0:256] @ W1[0:256,:]
    gemm_ca<4096, 2, 8>(g_wt, 16, As, Bs, acc, mb0, nb0, tid, lane);

    __syncthreads();

    // winding MLP -> frag-packed A cols 0..127
#pragma unroll 1
    for (int rr = 0; rr < 8; rr++) {
        int r = warp * 8 + rr, e = e0 + r;
        float w0 = 0.f, w1 = 0.f;
        if (e < E) { w0 = wind[(size_t)e * 2]; w1 = wind[(size_t)e * 2 + 1]; }
        float v[4], s = 0.f, q = 0.f;
#pragma unroll
        for (int j = 0; j < 4; j++) {
            int c = lane * 4 + j;
            float x = fmaf(w0, P[PWw + c], fmaf(w1, P[PWw + 128 + c], P[Pbw + c]));
            v[j] = x; s += x; q += x * x;
        }
#pragma unroll
        for (int o = 16; o; o >>= 1) {
            s += __shfl_xor_sync(~0u, s, o);
            q += __shfl_xor_sync(~0u, q, o);
        }
        float mu = s * (1.f / 128.f);
        float var = fmaf(-mu, mu, q * (1.f / 128.f));
        float rs = rsqrtf(var + 1e-5f);
        const int mb = r >> 4, gd = r & 7, hir = (r >> 3) & 1;
        const int kb = lane >> 1, hic = lane & 1;
        const int w = a_word(mb, kb) + gd * 16 + hir + 2 * hic;
#pragma unroll
        for (int j = 0; j < 4; j++) {
            int c = lane * 4 + j;
            As[w + j * 4] = f2tf(fmaxf(fmaf((v[j] - mu) * rs, P[Pgw + c], P[Ptw + c]), 0.f));
        }
    }

    // GEMM1 pass 2: w @ W1[256:384,:] (accumulate)
    gemm_ca<4096, 2, 8>(g_wt + 16 * 4096, 8, As, Bs, acc, mb0, nb0, tid, lane);

    __syncthreads();
    store_acc_frag<2, 8>(As, acc, P + Pb1, mb0, nb0, gid, tig);
    __syncthreads();
    ln_relu_frag(As, P + Pg1, P + Pt1, warp, lane);
    __syncthreads();

    // GEMM2
#pragma unroll
    for (int mt = 0; mt < 2; mt++)
#pragma unroll
        for (int nt = 0; nt < 8; nt++)
#pragma unroll
            for (int j = 0; j < 4; j++) acc[mt][nt][j] = 0.f;
    gemm_ca<4096, 2, 8>(g_wt + W2B, 16, As, Bs, acc, mb0, nb0, tid, lane);

    __syncthreads();
    store_acc_frag<2, 8>(As, acc, P + Pb2, mb0, nb0, gid, tig);
    __syncthreads();
    ln_relu_frag(As, P + Pg2, P + Pt2, warp, lane);
    __syncthreads();

    // GEMM3 (N=64)
    float acc3[2][2][4];
#pragma unroll
    for (int mt = 0; mt < 2; mt++)
#pragma unroll
        for (int nt = 0; nt < 2; nt++)
#pragma unroll
            for (int j = 0; j < 4; j++) acc3[mt][nt][j] = 0.f;
    const int nb03 = (warp & 3) * 2;
    gemm_ca<1024, 2, 2>(g_wt + W3B, 16, As, Bs, acc3, mb0, nb03, tid, lane);

#pragma unroll
    for (int mt = 0; mt < 2; mt++)
#pragma unroll
        for (int nt = 0; nt < 2; nt++) {
            int r0 = (warp >> 2) * 32 + mt * 16 + gid;
            int c0 = (nb03 + nt) * 8 + 2 * tig;
            int e = e0 + r0;
            if (e < E)
                *(float2*)(out + (size_t)e * 64 + c0) =
                    make_float2(acc3[mt][nt][0] + P[Pb3 + c0],
                                acc3[mt][nt][1] + P[Pb3 + c0 + 1]);
            e = e0 + r0 + 8;
            if (e < E)
                *(float2*)(out + (size_t)e * 64 + c0) =
                    make_float2(acc3[mt][nt][2] + P[Pb3 + c0],
                                acc3[mt][nt][3] + P[Pb3 + c0 + 1]);
        }
}

extern "C" void kernel_launch(void* const* d_in, const int* in_sizes, int n_in,
                              void* d_out, int out_size)
{
    const float* src = (const float*)d_in[0];
    const float* dst_ = (const float*)d_in[1];
    const float* ea = (const float*)d_in[2];
    const float* u = (const float*)d_in[3];
    const void* batch = d_in[4];
    const float* wind = (const float*)d_in[5];
    const float* Ww = (const float*)d_in[6];
    const float* bw = (const float*)d_in[7];
    const float* gw = (const float*)d_in[8];
    const float* btw = (const float*)d_in[9];
    const float* W1 = (const float*)d_in[10];
    const float* b1 = (const float*)d_in[11];
    const float* g1 = (const float*)d_in[12];
    const float* bt1 = (const float*)d_in[13];
    const float* W2 = (const float*)d_in[14];
    const float* b2 = (const float*)d_in[15];
    const float* g2 = (const float*)d_in[16];
    const float* bt2 = (const float*)d_in[17];
    const float* W3 = (const float*)d_in[18];
    const float* b3 = (const float*)d_in[19];
    const int E = in_sizes[0] / 64;

    cudaFuncSetAttribute(fused_edge_kernel,
                         cudaFuncAttributeMaxDynamicSharedMemorySize, SMEM_BYTES);

    detect_batch_kernel<<<1, 32>>>((const int*)batch);
    prep_weights<<<704, 256>>>(W1, W2, W3);

    fused_edge_kernel<<<(E + ROWS - 1) / ROWS, 256, SMEM_BYTES>>>(
        src, dst_, ea, u, batch, wind,
        bw, gw, btw, Ww,
        b1, g1, bt1, b2, g2, bt2, b3, (float*)d_out, E);
}

// round 7
// speedup vs baseline: 1.9549x; 1.1384x over previous
#include <cuda_runtime.h>
#include <cstdint>

namespace {

constexpr int ROWS = 64;           // edges per CTA
constexpr int BLKW = 132;          // words per A frag block (512B + 16B pad)
constexpr int A_OFF = 0;           // 4 mb x 32 kb blocks = 128*132 = 16896 floats
constexpr int P_OFF = 16896;       // 2240 params
constexpr int BSM_OFF = 19136;     // 64 batch ids
constexpr int SMF = 19200;
constexpr int SMEM_BYTES = SMF * 4;   // 76800 B -> 2 CTAs/SM

constexpr int Pb1 = 0, Pg1 = 256, Pt1 = 512, Pb2 = 768, Pg2 = 1024, Pt2 = 1280;
constexpr int Pb3 = 1536, PWw = 1600, Pbw = 1856, Pgw = 1984, Ptw = 2112;

// frag-packed tf32 weights: [kb][nb][64] per matrix
// W1: 48 kb x 32 nb, W2: 32 x 32, W3: 32 x 8
constexpr int W2B = 98304, W3B = 163840;
__device__ float g_wt[180224];
__device__ int g_is64;

__device__ __forceinline__ float f2tf(float f) {
    unsigned u; asm("cvt.rna.tf32.f32 %0, %1;" : "=r"(u) : "f"(f));
    return __uint_as_float(u);
}
__device__ __forceinline__ void mma8(float* d, const unsigned* a, unsigned b0, unsigned b1) {
    asm volatile(
        "mma.sync.aligned.m16n8k8.row.col.f32.tf32.tf32.f32 "
        "{%0,%1,%2,%3},{%4,%5,%6,%7},{%8,%9},{%0,%1,%2,%3};\n"
        : "+f"(d[0]), "+f"(d[1]), "+f"(d[2]), "+f"(d[3])
        : "r"(a[0]), "r"(a[1]), "r"(a[2]), "r"(a[3]), "r"(b0), "r"(b1));
}
__device__ __forceinline__ int a_word(int mb, int kb) { return (mb * 32 + kb) * BLKW; }

// Barrier-free GEMM mainloop: A frag-packed in smem, B frag-packed in gmem
// (one LDG.64 per (kb,nb) per warp), B register-double-buffered.
// acc persists across calls (caller zeroes / accumulates).
template <int NT>
__device__ __forceinline__ void gemm_ldg(
    const float* __restrict__ Wb, const int KB, const int nbstride,
    const float* __restrict__ As, float (&acc)[2][NT][4],
    const int nb0, const int warp, const int lane)
{
    const int mb0 = (warp >> 2) * 2;
    const float* wp = Wb + nb0 * 64 + lane * 2;
    float2 br0[NT], br1[NT];
#pragma unroll
    for (int nt = 0; nt < NT; nt++) br0[nt] = *(const float2*)(wp + nt * 64);

#pragma unroll 1
    for (int kb = 0; kb < KB; kb += 2) {
        // prefetch kb+1 -> br1 (KB even => kb+1 < KB)
        {
            const float* w1 = wp + (size_t)(kb + 1) * nbstride;
#pragma unroll
            for (int nt = 0; nt < NT; nt++) br1[nt] = *(const float2*)(w1 + nt * 64);
        }
        // compute kb with br0
        {
            unsigned a[2][4];
#pragma unroll
            for (int mt = 0; mt < 2; mt++) {
                float4 av = *(const float4*)(As + a_word(mb0 + mt, kb) + lane * 4);
                a[mt][0] = __float_as_uint(av.x); a[mt][1] = __float_as_uint(av.y);
                a[mt][2] = __float_as_uint(av.z); a[mt][3] = __float_as_uint(av.w);
            }
#pragma unroll
            for (int nt = 0; nt < NT; nt++) {
                unsigned bb0 = __float_as_uint(br0[nt].x);
                unsigned bb1 = __float_as_uint(br0[nt].y);
                mma8(acc[0][nt], a[0], bb0, bb1);
                mma8(acc[1][nt], a[1], bb0, bb1);
            }
        }
        // prefetch kb+2 -> br0 (clamped on last pair)
        {
            const int kn = (kb + 2 < KB) ? kb + 2 : kb + 1;
            const float* w2 = wp + (size_t)kn * nbstride;
#pragma unroll
            for (int nt = 0; nt < NT; nt++) br0[nt] = *(const float2*)(w2 + nt * 64);
        }
        // compute kb+1 with br1
        {
            unsigned a[2][4];
#pragma unroll
            for (int mt = 0; mt < 2; mt++) {
                float4 av = *(const float4*)(As + a_word(mb0 + mt, kb + 1) + lane * 4);
                a[mt][0] = __float_as_uint(av.x); a[mt][1] = __float_as_uint(av.y);
                a[mt][2] = __float_as_uint(av.z); a[mt][3] = __float_as_uint(av.w);
            }
#pragma unroll
            for (int nt = 0; nt < NT; nt++) {
                unsigned bb0 = __float_as_uint(br1[nt].x);
                unsigned bb1 = __float_as_uint(br1[nt].y);
                mma8(acc[0][nt], a[0], bb0, bb1);
                mma8(acc[1][nt], a[1], bb0, bb1);
            }
        }
    }
}

template <int MT, int NT>
__device__ __forceinline__ void store_acc_frag(
    float* __restrict__ A, const float (&acc)[MT][NT][4], const float* __restrict__ bias,
    int mb0, int nb0, int gid, int tig)
{
    const int base = gid * 16 + ((tig & 1) * 2) * 4 + 2 * (tig >> 1);
#pragma unroll
    for (int mt = 0; mt < MT; mt++)
#pragma unroll
        for (int nt = 0; nt < NT; nt++) {
            int c0 = (nb0 + nt) * 8 + 2 * tig;
            int w = a_word(mb0 + mt, nb0 + nt) + base;
            A[w]     = acc[mt][nt][0] + bias[c0];
            A[w + 4] = acc[mt][nt][1] + bias[c0 + 1];
            A[w + 1] = acc[mt][nt][2] + bias[c0];
            A[w + 5] = acc[mt][nt][3] + bias[c0 + 1];
        }
}

__device__ __forceinline__ void ln_relu_frag(
    float* __restrict__ A, const float* __restrict__ g, const float* __restrict__ b,
    int warp, int lane)
{
    const int mb = warp >> 1, hir = warp & 1;
    const int off = (lane & 3) * 4 + hir + 2 * ((lane >> 2) & 1);
    const int kbl = lane >> 3;
#pragma unroll 1
    for (int rr = 0; rr < 8; rr++) {
        const int wb = rr * 16 + off;
        float v[8], s = 0.f, q = 0.f;
#pragma unroll
        for (int j = 0; j < 8; j++) {
            float x = A[a_word(mb, kbl + 4 * j) + wb];
            v[j] = x; s += x; q += x * x;
        }
#pragma unroll
        for (int o = 16; o; o >>= 1) {
            s += __shfl_xor_sync(~0u, s, o);
            q += __shfl_xor_sync(~0u, q, o);
        }
        float mu = s * (1.f / 256.f);
        float var = fmaf(-mu, mu, q * (1.f / 256.f));
        float rs = rsqrtf(var + 1e-5f);
#pragma unroll
        for (int j = 0; j < 8; j++) {
            int c = lane + 32 * j;
            A[a_word(mb, kbl + 4 * j) + wb] =
                f2tf(fmaxf(fmaf((v[j] - mu) * rs, g[c], b[c]), 0.f));
        }
    }
}

}  // namespace

__global__ void detect_batch_kernel(const int* __restrict__ b32) {
    int bad = (b32[2 * threadIdx.x + 1] != 0);
    unsigned m = __ballot_sync(~0u, bad);
    if (threadIdx.x == 0) g_is64 = (m == 0);
}

// pack weights into [kb][nb][64] fragment blocks (tf32)
__global__ void prep_weights(const float* __restrict__ W1, const float* __restrict__ W2,
                             const float* __restrict__ W3) {
    int id = blockIdx.x * 256 + threadIdx.x;
    if (id >= 180224) return;
    const float* W; int t, ncols, nbshift;
    if (id < W2B)      { W = W1; t = id;       ncols = 256; nbshift = 11; }
    else if (id < W3B) { W = W2; t = id - W2B; ncols = 256; nbshift = 11; }
    else               { W = W3; t = id - W3B; ncols = 64;  nbshift = 9;  }
    int kb = t >> nbshift;
    int nb = (t >> 6) & ((1 << (nbshift - 6)) - 1);
    int j = t & 63, l = j >> 1, p = j & 1;
    int k = kb * 8 + (l & 3) + p * 4;
    int n = nb * 8 + (l >> 2);
    g_wt[id] = f2tf(W[k * ncols + n]);
}

__global__ void __launch_bounds__(256, 2)
fused_edge_kernel(const float* __restrict__ src, const float* __restrict__ dst_,
                  const float* __restrict__ ea, const float* __restrict__ u,
                  const void* __restrict__ braw, const float* __restrict__ wind,
                  const float* __restrict__ bw, const float* __restrict__ gw,
                  const float* __restrict__ btw, const float* __restrict__ Ww,
                  const float* __restrict__ b1, const float* __restrict__ g1,
                  const float* __restrict__ bt1, const float* __restrict__ b2,
                  const float* __restrict__ g2, const float* __restrict__ bt2,
                  const float* __restrict__ b3, float* __restrict__ out, int E)
{
    extern __shared__ float sm[];
    float* As = sm + A_OFF;
    float* P  = sm + P_OFF;
    int* bsm  = (int*)(sm + BSM_OFF);

    const int tid = threadIdx.x;
    const int warp = tid >> 5, lane = tid & 31;
    const int gid = lane >> 2, tig = lane & 3;
    const int e0 = blockIdx.x * ROWS;
    const int is64 = g_is64;

    if (tid < 256) {
        P[PWw + tid] = Ww[tid];
        P[Pb1 + tid] = b1[tid]; P[Pg1 + tid] = g1[tid]; P[Pt1 + tid] = bt1[tid];
        P[Pb2 + tid] = b2[tid]; P[Pg2 + tid] = g2[tid]; P[Pt2 + tid] = bt2[tid];
        if (tid < 128) { P[Pbw + tid] = bw[tid]; P[Pgw + tid] = gw[tid]; P[Ptw + tid] = btw[tid]; }
        if (tid < 64) {
            P[Pb3 + tid] = b3[tid];
            int e = e0 + tid;
            bsm[tid] = (e < E) ? (is64 ? (int)((const long long*)braw)[e]
                                       : ((const int*)braw)[e]) : 0;
        }
    }
    __syncthreads();

    // stage x: src|dest|ea|u[batch] -> frag-packed A cols 0..255 (tf32)
#pragma unroll 1
    for (int idx = tid; idx < ROWS * 16; idx += 256) {
        int r = idx >> 4, c4 = (idx & 15) * 4;
        int e = e0 + r;
        float4 vv[4];
        vv[0] = vv[1] = vv[2] = vv[3] = make_float4(0.f, 0.f, 0.f, 0.f);
        if (e < E) {
            size_t o = (size_t)e * 64 + c4;
            vv[0] = *(const float4*)(src + o);
            vv[1] = *(const float4*)(dst_ + o);
            vv[2] = *(const float4*)(ea + o);
        }
        vv[3] = *(const float4*)(u + (size_t)bsm[r] * 64 + c4);
        const int mb = r >> 4, gd = r & 7, hir = (r >> 3) & 1;
        const int hic = (c4 >> 2) & 1, kbq = c4 >> 3;
        const int wb = gd * 16 + hir + 2 * hic;
#pragma unroll
        for (int reg = 0; reg < 4; reg++) {
            int w = a_word(mb, reg * 8 + kbq) + wb;
            const float* vp = &vv[reg].x;
            As[w]      = f2tf(vp[0]);
            As[w + 4]  = f2tf(vp[1]);
            As[w + 8]  = f2tf(vp[2]);
            As[w + 12] = f2tf(vp[3]);
        }
    }
    __syncthreads();   // A published

    const int mb0 = (warp >> 2) * 2;
    const int nb0 = (warp & 3) * 8;

    float acc[2][8][4];
#pragma unroll
    for (int mt = 0; mt < 2; mt++)
#pragma unroll
        for (int nt = 0; nt < 8; nt++)
#pragma unroll
            for (int j = 0; j < 4; j++) acc[mt][nt][j] = 0.f;

    // GEMM1 pass 1: x[:,0:256] @ W1 kb 0..31 (barrier-free)
    gemm_ldg<8>(g_wt, 32, 2048, As, acc, nb0, warp, lane);

    __syncthreads();   // all pass-1 A reads done before overwriting kb 0..15

    // winding MLP -> frag-packed A cols 0..127
#pragma unroll 1
    for (int rr = 0; rr < 8; rr++) {
        int r = warp * 8 + rr, e = e0 + r;
        float w0 = 0.f, w1 = 0.f;
        if (e < E) { w0 = wind[(size_t)e * 2]; w1 = wind[(size_t)e * 2 + 1]; }
        float v[4], s = 0.f, q = 0.f;
#pragma unroll
        for (int j = 0; j < 4; j++) {
            int c = lane * 4 + j;
            float x = fmaf(w0, P[PWw + c], fmaf(w1, P[PWw + 128 + c], P[Pbw + c]));
            v[j] = x; s += x; q += x * x;
        }
#pragma unroll
        for (int o = 16; o; o >>= 1) {
            s += __shfl_xor_sync(~0u, s, o);
            q += __shfl_xor_sync(~0u, q, o);
        }
        float mu = s * (1.f / 128.f);
        float var = fmaf(-mu, mu, q * (1.f / 128.f));
        float rs = rsqrtf(var + 1e-5f);
        const int mb = r >> 4, gd = r & 7, hir = (r >> 3) & 1;
        const int kb = lane >> 1, hic = lane & 1;
        const int w = a_word(mb, kb) + gd * 16 + hir + 2 * hic;
#pragma unroll
        for (int j = 0; j < 4; j++) {
            int c = lane * 4 + j;
            As[w + j * 4] = f2tf(fmaxf(fmaf((v[j] - mu) * rs, P[Pgw + c], P[Ptw + c]), 0.f));
        }
    }
    __syncthreads();

    // GEMM1 pass 2: w @ W1 kb 32..47 (accumulate)
    gemm_ldg<8>(g_wt + 32 * 2048, 16, 2048, As, acc, nb0, warp, lane);

    __syncthreads();
    store_acc_frag<2, 8>(As, acc, P + Pb1, mb0, nb0, gid, tig);
    __syncthreads();
    ln_relu_frag(As, P + Pg1, P + Pt1, warp, lane);
    __syncthreads();

    // GEMM2
#pragma unroll
    for (int mt = 0; mt < 2; mt++)
#pragma unroll
        for (int nt = 0; nt < 8; nt++)
#pragma unroll
            for (int j = 0; j < 4; j++) acc[mt][nt][j] = 0.f;
    gemm_ldg<8>(g_wt + W2B, 32, 2048, As, acc, nb0, warp, lane);

    __syncthreads();
    store_acc_frag<2, 8>(As, acc, P + Pb2, mb0, nb0, gid, tig);
    __syncthreads();
    ln_relu_frag(As, P + Pg2, P + Pt2, warp, lane);
    __syncthreads();

    // GEMM3 (N=64)
    float acc3[2][2][4];
#pragma unroll
    for (int mt = 0; mt < 2; mt++)
#pragma unroll
        for (int nt = 0; nt < 2; nt++)
#pragma unroll
            for (int j = 0; j < 4; j++) acc3[mt][nt][j] = 0.f;
    const int nb03 = (warp & 3) * 2;
    gemm_ldg<2>(g_wt + W3B, 32, 512, As, acc3, nb03, warp, lane);

#pragma unroll
    for (int mt = 0; mt < 2; mt++)
#pragma unroll
        for (int nt = 0; nt < 2; nt++) {
            int r0 = (warp >> 2) * 32 + mt * 16 + gid;
            int c0 = (nb03 + nt) * 8 + 2 * tig;
            int e = e0 + r0;
            if (e < E)
                *(float2*)(out + (size_t)e * 64 + c0) =
                    make_float2(acc3[mt][nt][0] + P[Pb3 + c0],
                                acc3[mt][nt][1] + P[Pb3 + c0 + 1]);
            e = e0 + r0 + 8;
            if (e < E)
                *(float2*)(out + (size_t)e * 64 + c0) =
                    make_float2(acc3[mt][nt][2] + P[Pb3 + c0],
                                acc3[mt][nt][3] + P[Pb3 + c0 + 1]);
        }
}

extern "C" void kernel_launch(void* const* d_in, const int* in_sizes, int n_in,
                              void* d_out, int out_size)
{
    const float* src = (const float*)d_in[0];
    const float* dst_ = (const float*)d_in[1];
    const float* ea = (const float*)d_in[2];
    const float* u = (const float*)d_in[3];
    const void* batch = d_in[4];
    const float* wind = (const float*)d_in[5];
    const float* Ww = (const float*)d_in[6];
    const float* bw = (const float*)d_in[7];
    const float* gw = (const float*)d_in[8];
    const float* btw = (const float*)d_in[9];
    const float* W1 = (const float*)d_in[10];
    const float* b1 = (const float*)d_in[11];
    const float* g1 = (const float*)d_in[12];
    const float* bt1 = (const float*)d_in[13];
    const float* W2 = (const float*)d_in[14];
    const float* b2 = (const float*)d_in[15];
    const float* g2 = (const float*)d_in[16];
    const float* bt2 = (const float*)d_in[17];
    const float* W3 = (const float*)d_in[18];
    const float* b3 = (const float*)d_in[19];
    const int E = in_sizes[0] / 64;

    cudaFuncSetAttribute(fused_edge_kernel,
                         cudaFuncAttributeMaxDynamicSharedMemorySize, SMEM_BYTES);

    detect_batch_kernel<<<1, 32>>>((const int*)batch);
    prep_weights<<<704, 256>>>(W1, W2, W3);

    fused_edge_kernel<<<(E + ROWS - 1) / ROWS, 256, SMEM_BYTES>>>(
        src, dst_, ea, u, batch, wind,
        bw, gw, btw, Ww,
        b1, g1, bt1, b2, g2, bt2, b3, (float*)d_out, E);
}